// round 8
// baseline (speedup 1.0000x reference)
#include <cuda_runtime.h>
#include <math.h>

// ---------------------------------------------------------------------------
// Constants
// ---------------------------------------------------------------------------
#define SEQ   2048
#define HID   768
#define NQ    12
#define NKV   3
#define HD    64
#define QKVC  1152
#define NE    16
#define FF    1536
#define SLOTS 4096

// GEMM smem geometry (3-stage pipeline)
#define SA_STRIDE 20
#define SB_STRIDE 136          // 8c+8ni+g -> conflict-free B frags
#define SA_STAGE  (128 * SA_STRIDE)
#define SB_STAGE  (16 * SB_STRIDE)
#define SMEM_SINGLE_B ((3 * SA_STAGE + 3 * SB_STAGE) * 4)
#define SMEM_DUAL_B   ((3 * SA_STAGE + 6 * SB_STAGE) * 4)

// ---------------------------------------------------------------------------
// Device scratch
// ---------------------------------------------------------------------------
__device__ float g_xn1[SEQ * HID];
__device__ float g_Q[NQ * SEQ * HD];
__device__ float g_K[NKV * SEQ * HD];
__device__ float g_V[NKV * SEQ * HD];
__device__ float g_attn[SEQ * HID];
__device__ float g_h1[SEQ * HID];
__device__ float g_xn2[SEQ * HID];
__device__ int   g_eid[SLOTS];
__device__ float g_ew[SLOTS];
__device__ int   g_cnt[NE];
__device__ int   g_off[NE + 1];
__device__ int   g_cur[NE];
__device__ int   g_ptok[SLOTS];
__device__ int   g_tslot[SLOTS];
__device__ float g_Hact[(size_t)SLOTS * FF];
__device__ float g_Dn[(size_t)SLOTS * HID];

// ---------------------------------------------------------------------------
// Helpers
// ---------------------------------------------------------------------------
__device__ __forceinline__ void mma_tf32(float d[4], const unsigned a[4],
                                         const unsigned b[2]) {
    asm volatile(
        "mma.sync.aligned.m16n8k8.row.col.f32.tf32.tf32.f32 "
        "{%0,%1,%2,%3}, {%4,%5,%6,%7}, {%8,%9}, {%0,%1,%2,%3};"
        : "+f"(d[0]), "+f"(d[1]), "+f"(d[2]), "+f"(d[3])
        : "r"(a[0]), "r"(a[1]), "r"(a[2]), "r"(a[3]),
          "r"(b[0]), "r"(b[1]));
}

__device__ __forceinline__ void cp16(void* smem_dst, const void* gmem_src, bool pred) {
    unsigned d = (unsigned)__cvta_generic_to_shared(smem_dst);
    int sz = pred ? 16 : 0;
    asm volatile("cp.async.cg.shared.global [%0], [%1], 16, %2;"
                 :: "r"(d), "l"(gmem_src), "r"(sz) : "memory");
}

// ---------------------------------------------------------------------------
// RMSNorm 1
// ---------------------------------------------------------------------------
__global__ void k_rmsnorm1(const float* __restrict__ x, const float* __restrict__ w) {
    int row = blockIdx.x;
    const float* xr = x + (size_t)row * HID;
    float s = 0.f;
    for (int i = threadIdx.x; i < HID; i += 256) {
        float v = xr[i];
        s += v * v;
    }
    __shared__ float red[256];
    red[threadIdx.x] = s;
    __syncthreads();
    for (int o = 128; o > 0; o >>= 1) {
        if (threadIdx.x < o) red[threadIdx.x] += red[threadIdx.x + o];
        __syncthreads();
    }
    float scale = rsqrtf(red[0] / (float)HID + 1e-6f);
    for (int i = threadIdx.x; i < HID; i += 256)
        g_xn1[(size_t)row * HID + i] = xr[i] * scale * w[i];
}

// ---------------------------------------------------------------------------
// Single-B TF32 GEMM core (3-stage cp.async). Pointers pre-offset per thread.
// ---------------------------------------------------------------------------
__device__ __forceinline__ void gemm_single3(
    const float* Ar0, const float* Ar1, bool p0, bool p1,
    const float* Br0, const float* Br1, int ldb,
    int K, unsigned* SA, unsigned* SB, float acc[4][4][4])
{
    int tid = threadIdx.x;
    int warp = tid >> 5, lane = tid & 31;
    int wm = warp >> 2, wn = warp & 3;
    int g = lane >> 2, c = lane & 3;
    int ar0 = tid >> 2, ar1 = ar0 + 64;
    int akq = (tid & 3) * 4;
    int bkr0 = tid >> 5, bkr1 = bkr0 + 8;
    int bc4 = (tid & 31) * 4;

#define ST1(s, k0)                                                            \
    do {                                                                      \
        unsigned* a_ = SA + (s) * SA_STAGE;                                   \
        unsigned* b_ = SB + (s) * SB_STAGE;                                   \
        cp16(a_ + ar0 * SA_STRIDE + akq, Ar0 + (k0), p0);                     \
        cp16(a_ + ar1 * SA_STRIDE + akq, Ar1 + (k0), p1);                     \
        cp16(b_ + bkr0 * SB_STRIDE + bc4, Br0 + (size_t)(k0) * ldb, true);    \
        cp16(b_ + bkr1 * SB_STRIDE + bc4, Br1 + (size_t)(k0) * ldb, true);    \
        asm volatile("cp.async.commit_group;" ::: "memory");                  \
    } while (0)

    ST1(0, 0);
    ST1(1, 16);
    int buf = 0;
    for (int k0 = 0; k0 < K; k0 += 16) {
        if (k0 + 32 < K) {
            asm volatile("cp.async.wait_group 1;" ::: "memory");
            __syncthreads();
            ST1(buf == 0 ? 2 : buf - 1, k0 + 32);
        } else {
            asm volatile("cp.async.wait_group 0;" ::: "memory");
            __syncthreads();
        }
        unsigned* a_ = SA + buf * SA_STAGE;
        unsigned* b_ = SB + buf * SB_STAGE;
#pragma unroll
        for (int kk = 0; kk < 16; kk += 8) {
            unsigned af[4][4];
#pragma unroll
            for (int mi = 0; mi < 4; mi++) {
                int m = wm * 64 + mi * 16;
                af[mi][0] = a_[(m + g) * SA_STRIDE + kk + c];
                af[mi][1] = a_[(m + g + 8) * SA_STRIDE + kk + c];
                af[mi][2] = a_[(m + g) * SA_STRIDE + kk + c + 4];
                af[mi][3] = a_[(m + g + 8) * SA_STRIDE + kk + c + 4];
            }
#pragma unroll
            for (int ni = 0; ni < 4; ni++) {
                int n = wn * 32 + ni * 8 + g;
                unsigned bf[2];
                bf[0] = b_[(kk + c) * SB_STRIDE + n];
                bf[1] = b_[(kk + c + 4) * SB_STRIDE + n];
#pragma unroll
                for (int mi = 0; mi < 4; mi++)
                    mma_tf32(acc[mi][ni], af[mi], bf);
            }
        }
        buf = (buf == 2) ? 0 : buf + 1;
    }
#undef ST1
}

// ---------------------------------------------------------------------------
// Dual-B TF32 GEMM core (shared A fragments over two column panels)
// ---------------------------------------------------------------------------
__device__ __forceinline__ void gemm_dual3(
    const float* Ar0, const float* Ar1, bool p0, bool p1,
    const float* B0r0, const float* B0r1,
    const float* B1r0, const float* B1r1, int ldb,
    int K, unsigned* SA, unsigned* SB0, unsigned* SB1,
    float accg[4][4][4], float accu[4][4][4])
{
    int tid = threadIdx.x;
    int warp = tid >> 5, lane = tid & 31;
    int wm = warp >> 2, wn = warp & 3;
    int g = lane >> 2, c = lane & 3;
    int ar0 = tid >> 2, ar1 = ar0 + 64;
    int akq = (tid & 3) * 4;
    int bkr0 = tid >> 5, bkr1 = bkr0 + 8;
    int bc4 = (tid & 31) * 4;

#define STD(s, k0)                                                            \
    do {                                                                      \
        unsigned* a_  = SA + (s) * SA_STAGE;                                  \
        unsigned* b0_ = SB0 + (s) * SB_STAGE;                                 \
        unsigned* b1_ = SB1 + (s) * SB_STAGE;                                 \
        cp16(a_ + ar0 * SA_STRIDE + akq, Ar0 + (k0), p0);                     \
        cp16(a_ + ar1 * SA_STRIDE + akq, Ar1 + (k0), p1);                     \
        cp16(b0_ + bkr0 * SB_STRIDE + bc4, B0r0 + (size_t)(k0) * ldb, true);  \
        cp16(b0_ + bkr1 * SB_STRIDE + bc4, B0r1 + (size_t)(k0) * ldb, true);  \
        cp16(b1_ + bkr0 * SB_STRIDE + bc4, B1r0 + (size_t)(k0) * ldb, true);  \
        cp16(b1_ + bkr1 * SB_STRIDE + bc4, B1r1 + (size_t)(k0) * ldb, true);  \
        asm volatile("cp.async.commit_group;" ::: "memory");                  \
    } while (0)

    STD(0, 0);
    STD(1, 16);
    int buf = 0;
    for (int k0 = 0; k0 < K; k0 += 16) {
        if (k0 + 32 < K) {
            asm volatile("cp.async.wait_group 1;" ::: "memory");
            __syncthreads();
            STD(buf == 0 ? 2 : buf - 1, k0 + 32);
        } else {
            asm volatile("cp.async.wait_group 0;" ::: "memory");
            __syncthreads();
        }
        unsigned* a_  = SA + buf * SA_STAGE;
        unsigned* b0_ = SB0 + buf * SB_STAGE;
        unsigned* b1_ = SB1 + buf * SB_STAGE;
#pragma unroll
        for (int kk = 0; kk < 16; kk += 8) {
            unsigned af[4][4];
#pragma unroll
            for (int mi = 0; mi < 4; mi++) {
                int m = wm * 64 + mi * 16;
                af[mi][0] = a_[(m + g) * SA_STRIDE + kk + c];
                af[mi][1] = a_[(m + g + 8) * SA_STRIDE + kk + c];
                af[mi][2] = a_[(m + g) * SA_STRIDE + kk + c + 4];
                af[mi][3] = a_[(m + g + 8) * SA_STRIDE + kk + c + 4];
            }
#pragma unroll
            for (int ni = 0; ni < 4; ni++) {
                int n = wn * 32 + ni * 8 + g;
                unsigned bf0[2], bf1[2];
                bf0[0] = b0_[(kk + c) * SB_STRIDE + n];
                bf0[1] = b0_[(kk + c + 4) * SB_STRIDE + n];
                bf1[0] = b1_[(kk + c) * SB_STRIDE + n];
                bf1[1] = b1_[(kk + c + 4) * SB_STRIDE + n];
#pragma unroll
                for (int mi = 0; mi < 4; mi++) {
                    mma_tf32(accg[mi][ni], af[mi], bf0);
                    mma_tf32(accu[mi][ni], af[mi], bf1);
                }
            }
        }
        buf = (buf == 2) ? 0 : buf + 1;
    }
#undef STD
}

// ---------------------------------------------------------------------------
// QKV projection + fused RoPE epilogue -> g_Q / g_K / g_V (head-major)
// ---------------------------------------------------------------------------
__global__ void __launch_bounds__(256) k_gemm_qkv(const float* __restrict__ W) {
    extern __shared__ unsigned dsm[];
    int mb = blockIdx.x, nb = blockIdx.y;
    int tid = threadIdx.x;
    float acc[4][4][4] = {};
    {
        int ar0 = tid >> 2, ar1 = ar0 + 64;
        int akq = (tid & 3) * 4;
        int bkr0 = tid >> 5, bkr1 = bkr0 + 8;
        int bc4 = (tid & 31) * 4;
        const float* A = g_xn1 + (size_t)mb * 128 * HID;
        const float* B = W + nb * 128;
        gemm_single3(A + (size_t)ar0 * HID + akq, A + (size_t)ar1 * HID + akq,
                     true, true,
                     B + (size_t)bkr0 * QKVC + bc4, B + (size_t)bkr1 * QKVC + bc4,
                     QKVC, HID, dsm, dsm + 3 * SA_STAGE, acc);
    }
    int warp = tid >> 5, lane = tid & 31;
    int wm = warp >> 2, wn = warp & 3, g = lane >> 2, c = lane & 3;
#pragma unroll
    for (int mi = 0; mi < 4; mi++) {
#pragma unroll
        for (int ni = 0; ni < 4; ni++) {
            int r   = mb * 128 + wm * 64 + mi * 16 + g;
            int col = nb * 128 + wn * 32 + ni * 8 + 2 * c;
            int dm  = col & 63;
            float a0 = acc[mi][ni][0], a1 = acc[mi][ni][1];
            float b0 = acc[mi][ni][2], b1 = acc[mi][ni][3];
            if (col < NQ * HD) {
                int hh = col >> 6;
                float inv = powf(10000.f, -(float)dm / 64.f);
                float sn0, cs0, sn1, cs1;
                sincosf((float)r * inv, &sn0, &cs0);
                sincosf((float)(r + 8) * inv, &sn1, &cs1);
                float* d0 = g_Q + ((size_t)hh * SEQ + r) * HD + dm;
                float* d1 = g_Q + ((size_t)hh * SEQ + r + 8) * HD + dm;
                *reinterpret_cast<float2*>(d0) = make_float2(a0 * cs0 - a1 * sn0, a0 * sn0 + a1 * cs0);
                *reinterpret_cast<float2*>(d1) = make_float2(b0 * cs1 - b1 * sn1, b0 * sn1 + b1 * cs1);
            } else if (col < (NQ + NKV) * HD) {
                int hh = (col - NQ * HD) >> 6;
                float inv = powf(10000.f, -(float)dm / 64.f);
                float sn0, cs0, sn1, cs1;
                sincosf((float)r * inv, &sn0, &cs0);
                sincosf((float)(r + 8) * inv, &sn1, &cs1);
                float* d0 = g_K + ((size_t)hh * SEQ + r) * HD + dm;
                float* d1 = g_K + ((size_t)hh * SEQ + r + 8) * HD + dm;
                *reinterpret_cast<float2*>(d0) = make_float2(a0 * cs0 - a1 * sn0, a0 * sn0 + a1 * cs0);
                *reinterpret_cast<float2*>(d1) = make_float2(b0 * cs1 - b1 * sn1, b0 * sn1 + b1 * cs1);
            } else {
                int hh = (col - (NQ + NKV) * HD) >> 6;
                float* d0 = g_V + ((size_t)hh * SEQ + r) * HD + dm;
                float* d1 = g_V + ((size_t)hh * SEQ + r + 8) * HD + dm;
                *reinterpret_cast<float2*>(d0) = make_float2(a0, a1);
                *reinterpret_cast<float2*>(d1) = make_float2(b0, b1);
            }
        }
    }
}

// ---------------------------------------------------------------------------
// Out projection + residual (dual-B): g_h1 = x + g_attn @ w_out
// ---------------------------------------------------------------------------
__global__ void __launch_bounds__(256) k_gemm_out(const float* __restrict__ W,
                                                  const float* __restrict__ xres) {
    extern __shared__ unsigned dsm[];
    int mb = blockIdx.x, nb = blockIdx.y;
    int tid = threadIdx.x;
    float accg[4][4][4] = {};
    float accu[4][4][4] = {};
    {
        int ar0 = tid >> 2, ar1 = ar0 + 64;
        int akq = (tid & 3) * 4;
        int bkr0 = tid >> 5, bkr1 = bkr0 + 8;
        int bc4 = (tid & 31) * 4;
        const float* A  = g_attn + (size_t)mb * 128 * HID;
        const float* B0 = W + nb * 128;
        const float* B1 = B0 + 384;
        gemm_dual3(A + (size_t)ar0 * HID + akq, A + (size_t)ar1 * HID + akq, true, true,
                   B0 + (size_t)bkr0 * HID + bc4, B0 + (size_t)bkr1 * HID + bc4,
                   B1 + (size_t)bkr0 * HID + bc4, B1 + (size_t)bkr1 * HID + bc4,
                   HID, HID, dsm, dsm + 3 * SA_STAGE, dsm + 3 * SA_STAGE + 3 * SB_STAGE,
                   accg, accu);
    }
    int warp = tid >> 5, lane = tid & 31;
    int wm = warp >> 2, wn = warp & 3, g = lane >> 2, c = lane & 3;
#pragma unroll
    for (int mi = 0; mi < 4; mi++) {
#pragma unroll
        for (int ni = 0; ni < 4; ni++) {
            int r = mb * 128 + wm * 64 + mi * 16 + g;
            int col0 = nb * 128 + wn * 32 + ni * 8 + 2 * c;
#pragma unroll
            for (int half = 0; half < 2; half++) {
                float* ac = half ? accu[mi][ni] : accg[mi][ni];
                int col = col0 + half * 384;
                size_t o0 = (size_t)r * HID + col;
                size_t o1 = (size_t)(r + 8) * HID + col;
                float2 x0 = *reinterpret_cast<const float2*>(xres + o0);
                float2 x1 = *reinterpret_cast<const float2*>(xres + o1);
                *reinterpret_cast<float2*>(g_h1 + o0) = make_float2(x0.x + ac[0], x0.y + ac[1]);
                *reinterpret_cast<float2*>(g_h1 + o1) = make_float2(x1.x + ac[2], x1.y + ac[3]);
            }
        }
    }
}

// ---------------------------------------------------------------------------
// MoE GEMM1 (indirect A rows via ptok) fused with SiLU*up -> g_Hact
// ---------------------------------------------------------------------------
__global__ void __launch_bounds__(256) k_moe_gemm1(const float* __restrict__ Wgu) {
    extern __shared__ unsigned dsm[];
    __shared__ int sptok[128];
    int e = blockIdx.x >> 4, mb = blockIdx.x & 15, nb = blockIdx.y;
    int r0 = g_off[e];
    int rows_e = g_off[e + 1] - r0;
    int rbase = mb * 128;
    if (rbase >= rows_e) return;
    int rows = min(128, rows_e - rbase);
    int tid = threadIdx.x;
    if (tid < 128) sptok[tid] = (tid < rows) ? g_ptok[r0 + rbase + tid] : 0;
    __syncthreads();

    float accg[4][4][4] = {};
    float accu[4][4][4] = {};
    {
        int ar0 = tid >> 2, ar1 = ar0 + 64;
        int akq = (tid & 3) * 4;
        int bkr0 = tid >> 5, bkr1 = bkr0 + 8;
        int bc4 = (tid & 31) * 4;
        bool p0 = ar0 < rows, p1 = ar1 < rows;
        const float* Ar0 = g_xn2 + (size_t)sptok[ar0] * HID + akq;
        const float* Ar1 = g_xn2 + (size_t)sptok[ar1] * HID + akq;
        const float* Bg = Wgu + (size_t)e * HID * (2 * FF) + nb * 128;
        const float* Bu = Bg + FF;
        gemm_dual3(Ar0, Ar1, p0, p1,
                   Bg + (size_t)bkr0 * (2 * FF) + bc4, Bg + (size_t)bkr1 * (2 * FF) + bc4,
                   Bu + (size_t)bkr0 * (2 * FF) + bc4, Bu + (size_t)bkr1 * (2 * FF) + bc4,
                   2 * FF, HID, dsm, dsm + 3 * SA_STAGE, dsm + 3 * SA_STAGE + 3 * SB_STAGE,
                   accg, accu);
    }
    int warp = tid >> 5, lane = tid & 31;
    int wm = warp >> 2, wn = warp & 3, g = lane >> 2, c = lane & 3;
    float* Cp = g_Hact + (size_t)(r0 + rbase) * FF + nb * 128;
#pragma unroll
    for (int mi = 0; mi < 4; mi++) {
#pragma unroll
        for (int ni = 0; ni < 4; ni++) {
            int rr = wm * 64 + mi * 16 + g;
            int col = wn * 32 + ni * 8 + 2 * c;
            float h[4];
#pragma unroll
            for (int j = 0; j < 4; j++) {
                float gv = accg[mi][ni][j];
                h[j] = gv / (1.f + __expf(-gv)) * accu[mi][ni][j];
            }
            if (rr < rows)
                *reinterpret_cast<float2*>(Cp + (size_t)rr * FF + col) =
                    make_float2(h[0], h[1]);
            if (rr + 8 < rows)
                *reinterpret_cast<float2*>(Cp + (size_t)(rr + 8) * FF + col) =
                    make_float2(h[2], h[3]);
        }
    }
}

// ---------------------------------------------------------------------------
// MoE GEMM2 (dual-B): Dn[slot] = Hact[slot] @ w_down[e]
// ---------------------------------------------------------------------------
__global__ void __launch_bounds__(256) k_moe_gemm2(const float* __restrict__ Wd) {
    extern __shared__ unsigned dsm[];
    int e = blockIdx.x >> 4, mb = blockIdx.x & 15, nb = blockIdx.y;
    int r0 = g_off[e];
    int rows_e = g_off[e + 1] - r0;
    int rbase = mb * 128;
    if (rbase >= rows_e) return;
    int rows = min(128, rows_e - rbase);
    int tid = threadIdx.x;
    float accg[4][4][4] = {};
    float accu[4][4][4] = {};
    {
        int ar0 = tid >> 2, ar1 = ar0 + 64;
        int akq = (tid & 3) * 4;
        int bkr0 = tid >> 5, bkr1 = bkr0 + 8;
        int bc4 = (tid & 31) * 4;
        bool p0 = ar0 < rows, p1 = ar1 < rows;
        const float* A = g_Hact + (size_t)(r0 + rbase) * FF;
        const float* Ar0 = A + (size_t)(p0 ? ar0 : 0) * FF + akq;
        const float* Ar1 = A + (size_t)(p1 ? ar1 : 0) * FF + akq;
        const float* B0 = Wd + (size_t)e * FF * HID + nb * 128;
        const float* B1 = B0 + 384;
        gemm_dual3(Ar0, Ar1, p0, p1,
                   B0 + (size_t)bkr0 * HID + bc4, B0 + (size_t)bkr1 * HID + bc4,
                   B1 + (size_t)bkr0 * HID + bc4, B1 + (size_t)bkr1 * HID + bc4,
                   HID, FF, dsm, dsm + 3 * SA_STAGE, dsm + 3 * SA_STAGE + 3 * SB_STAGE,
                   accg, accu);
    }
    int warp = tid >> 5, lane = tid & 31;
    int wm = warp >> 2, wn = warp & 3, g = lane >> 2, c = lane & 3;
    float* Cp = g_Dn + (size_t)(r0 + rbase) * HID + nb * 128;
#pragma unroll
    for (int mi = 0; mi < 4; mi++) {
#pragma unroll
        for (int ni = 0; ni < 4; ni++) {
            int rr = wm * 64 + mi * 16 + g;
            int col0 = wn * 32 + ni * 8 + 2 * c;
#pragma unroll
            for (int half = 0; half < 2; half++) {
                float* ac = half ? accu[mi][ni] : accg[mi][ni];
                int col = col0 + half * 384;
                if (rr < rows)
                    *reinterpret_cast<float2*>(Cp + (size_t)rr * HID + col) =
                        make_float2(ac[0], ac[1]);
                if (rr + 8 < rows)
                    *reinterpret_cast<float2*>(Cp + (size_t)(rr + 8) * HID + col) =
                        make_float2(ac[2], ac[3]);
            }
        }
    }
}

// ---------------------------------------------------------------------------
// Flash attention, TF32 tensor cores, cp.async double-buffered K/V.
// smem strides: Q/K/P = 68 (4g+c conflict-free), V = 72 (8c+g conflict-free).
// ---------------------------------------------------------------------------
#define ATT_W ((64 * 68) * 4 + (64 * 72) * 2 + 64 * 65 + 3 * 64)
#define ATT_SMEM_BYTES (ATT_W * 4)

__global__ void k_attn(void) {
    extern __shared__ unsigned smu[];
    unsigned* uQ  = smu;                    // [64][68]
    unsigned* uK0 = uQ + 64 * 68;           // [64][68]
    unsigned* uK1 = uK0 + 64 * 68;
    unsigned* uP  = uK1 + 64 * 68;          // [64][68]
    unsigned* uV0 = uP + 64 * 68;           // [64][72]
    unsigned* uV1 = uV0 + 64 * 72;
    float* Sm    = (float*)(uV1 + 64 * 72); // [64][65]
    float* mrow  = Sm + 64 * 65;
    float* lrow  = mrow + 64;
    float* arow  = lrow + 64;

    int qb = gridDim.x - 1 - blockIdx.x;
    int h  = blockIdx.y;
    int kvh = h >> 2;
    int tid = threadIdx.x;
    int warp = tid >> 5, lane = tid & 31;
    int wm = warp >> 2, wn = warp & 3;
    int g  = lane >> 2, c = lane & 3;

    const float* Kbase = g_K + (size_t)kvh * SEQ * HD;
    const float* Vbase = g_V + (size_t)kvh * SEQ * HD;

#define ATT_ISSUE(buf_, kb_)                                                  \
    do {                                                                      \
        unsigned* dK = (buf_) ? uK1 : uK0;                                    \
        unsigned* dV = (buf_) ? uV1 : uV0;                                    \
        const float* Kb_ = Kbase + (size_t)(kb_) * 64 * HD;                   \
        const float* Vb_ = Vbase + (size_t)(kb_) * 64 * HD;                   \
        _Pragma("unroll")                                                     \
        for (int it = 0; it < 4; it++) {                                      \
            int e_ = tid + it * 256;                                          \
            int r_ = e_ >> 4;                                                 \
            int q_ = (e_ & 15) * 4;                                           \
            cp16(dK + r_ * 68 + q_, Kb_ + r_ * HD + q_, true);                \
            cp16(dV + r_ * 72 + q_, Vb_ + r_ * HD + q_, true);                \
        }                                                                     \
        asm volatile("cp.async.commit_group;" ::: "memory");                  \
    } while (0)

    ATT_ISSUE(0, 0);
    if (qb > 0) ATT_ISSUE(1, 1);

    const float* Qb = g_Q + ((size_t)h * SEQ + qb * 64) * HD;
    for (int e = tid; e < 4096; e += 256) {
        int r = e >> 6, d = e & 63;
        uQ[r * 68 + d] = __float_as_uint(Qb[r * HD + d] * 0.125f);
    }
    if (tid < 64) { mrow[tid] = -1e30f; lrow[tid] = 0.f; }

    float oacc[2][2][4] = {};
    for (int kb = 0; kb <= qb; kb++) {
        int buf = kb & 1;
        if (kb < qb)
            asm volatile("cp.async.wait_group 1;" ::: "memory");
        else
            asm volatile("cp.async.wait_group 0;" ::: "memory");
        __syncthreads();
        unsigned* cK = buf ? uK1 : uK0;
        unsigned* cV = buf ? uV1 : uV0;

        // ---- S = Q @ K^T ----
        float sacc[2][2][4] = {};
#pragma unroll
        for (int kk = 0; kk < 64; kk += 8) {
            unsigned af[2][4];
#pragma unroll
            for (int mi = 0; mi < 2; mi++) {
                int m = wm * 32 + mi * 16;
                af[mi][0] = uQ[(m + g) * 68 + kk + c];
                af[mi][1] = uQ[(m + g + 8) * 68 + kk + c];
                af[mi][2] = uQ[(m + g) * 68 + kk + c + 4];
                af[mi][3] = uQ[(m + g + 8) * 68 + kk + c + 4];
            }
#pragma unroll
            for (int ni = 0; ni < 2; ni++) {
                int n = wn * 16 + ni * 8 + g;
                unsigned bf[2];
                bf[0] = cK[n * 68 + kk + c];
                bf[1] = cK[n * 68 + kk + c + 4];
#pragma unroll
                for (int mi = 0; mi < 2; mi++)
                    mma_tf32(sacc[mi][ni], af[mi], bf);
            }
        }
        bool diag = (kb == qb);
#pragma unroll
        for (int mi = 0; mi < 2; mi++) {
#pragma unroll
            for (int ni = 0; ni < 2; ni++) {
                int r0 = wm * 32 + mi * 16 + g;
                int cl = wn * 16 + ni * 8 + 2 * c;
                float v0 = sacc[mi][ni][0], v1 = sacc[mi][ni][1];
                float v2 = sacc[mi][ni][2], v3 = sacc[mi][ni][3];
                if (diag) {
                    if (cl > r0)     v0 = -1e30f;
                    if (cl + 1 > r0) v1 = -1e30f;
                    if (cl > r0 + 8)     v2 = -1e30f;
                    if (cl + 1 > r0 + 8) v3 = -1e30f;
                }
                Sm[r0 * 65 + cl]           = v0;
                Sm[r0 * 65 + cl + 1]       = v1;
                Sm[(r0 + 8) * 65 + cl]     = v2;
                Sm[(r0 + 8) * 65 + cl + 1] = v3;
            }
        }
        __syncthreads();

        // ---- online softmax (4 lanes/row) ----
        {
            int i  = tid >> 2;
            int jq = (tid & 3) * 16;
            float mx = -1e30f;
#pragma unroll
            for (int j = 0; j < 16; j++) mx = fmaxf(mx, Sm[i * 65 + jq + j]);
            mx = fmaxf(mx, __shfl_xor_sync(0xffffffffu, mx, 1));
            mx = fmaxf(mx, __shfl_xor_sync(0xffffffffu, mx, 2));
            float mold = mrow[i];
            mx = fmaxf(mx, mold);
            float sum = 0.f;
#pragma unroll
            for (int j = 0; j < 16; j++) {
                float p = __expf(Sm[i * 65 + jq + j] - mx);
                uP[i * 68 + jq + j] = __float_as_uint(p);
                sum += p;
            }
            sum += __shfl_xor_sync(0xffffffffu, sum, 1);
            sum += __shfl_xor_sync(0xffffffffu, sum, 2);
            if ((tid & 3) == 0) {
                float al = __expf(mold - mx);
                lrow[i] = lrow[i] * al + sum;
                mrow[i] = mx;
                arow[i] = al;
            }
        }
        __syncthreads();

        // ---- rescale + O += P @ V ----
#pragma unroll
        for (int mi = 0; mi < 2; mi++) {
            float a0 = arow[wm * 32 + mi * 16 + g];
            float a1 = arow[wm * 32 + mi * 16 + g + 8];
#pragma unroll
            for (int ni = 0; ni < 2; ni++) {
                oacc[mi][ni][0] *= a0;
                oacc[mi][ni][1] *= a0;
                oacc[mi][ni][2] *= a1;
                oacc[mi][ni][3] *= a1;
            }
        }
#pragma unroll
        for (int kk = 0; kk < 64; kk += 8) {
            unsigned af[2][4];
#pragma unroll
            for (int mi = 0; mi < 2; mi++) {
                int m = wm * 32 + mi * 16;
                af[mi][0] = uP[(m + g) * 68 + kk + c];
                af[mi][1] = uP[(m + g + 8) * 68 + kk + c];
                af[mi][2] = uP[(m + g) * 68 + kk + c + 4];
                af[mi][3] = uP[(m + g + 8) * 68 + kk + c + 4];
            }
#pragma unroll
            for (int ni = 0; ni < 2; ni++) {
                int n = wn * 16 + ni * 8 + g;
                unsigned bf[2];
                bf[0] = cV[(kk + c) * 72 + n];
                bf[1] = cV[(kk + c + 4) * 72 + n];
#pragma unroll
                for (int mi = 0; mi < 2; mi++)
                    mma_tf32(oacc[mi][ni], af[mi], bf);
            }
        }
        // prefetch kb+2 into this buffer (all reads of it are done)
        if (kb + 2 <= qb) {
            __syncthreads();
            ATT_ISSUE(buf, kb + 2);
        }
    }

    __syncthreads();
#pragma unroll
    for (int mi = 0; mi < 2; mi++) {
        int rl0 = wm * 32 + mi * 16 + g;
        float i0 = 1.f / lrow[rl0];
        float i1 = 1.f / lrow[rl0 + 8];
        int gr0 = qb * 64 + rl0;
#pragma unroll
        for (int ni = 0; ni < 2; ni++) {
            int col = h * HD + wn * 16 + ni * 8 + 2 * c;
            *reinterpret_cast<float2*>(g_attn + (size_t)gr0 * HID + col) =
                make_float2(oacc[mi][ni][0] * i0, oacc[mi][ni][1] * i0);
            *reinterpret_cast<float2*>(g_attn + (size_t)(gr0 + 8) * HID + col) =
                make_float2(oacc[mi][ni][2] * i1, oacc[mi][ni][3] * i1);
        }
    }
#undef ATT_ISSUE
}

// ---------------------------------------------------------------------------
// Fused RMSNorm2 + router (fp32)
// ---------------------------------------------------------------------------
__global__ void k_rms2router(const float* __restrict__ w, const float* __restrict__ Wr) {
    int t = blockIdx.x;
    int tid = threadIdx.x;
    __shared__ float sxn[HID];
    __shared__ float red[256];
    __shared__ float lg[NE];
    const float* xr = g_h1 + (size_t)t * HID;
    float s = 0.f;
    for (int i = tid; i < HID; i += 256) {
        float v = xr[i];
        s += v * v;
    }
    red[tid] = s;
    __syncthreads();
    for (int o = 128; o > 0; o >>= 1) {
        if (tid < o) red[tid] += red[tid + o];
        __syncthreads();
    }
    float scale = rsqrtf(red[0] / (float)HID + 1e-6f);
    for (int i = tid; i < HID; i += 256) {
        float v = xr[i] * scale * w[i];
        sxn[i] = v;
        g_xn2[(size_t)t * HID + i] = v;
    }
    __syncthreads();
    int warp = tid >> 5, lane = tid & 31;
    float s0 = 0.f, s1 = 0.f;
    for (int k = lane; k < HID; k += 32) {
        float xv = sxn[k];
        s0 += xv * Wr[k * NE + 2 * warp];
        s1 += xv * Wr[k * NE + 2 * warp + 1];
    }
#pragma unroll
    for (int o = 16; o > 0; o >>= 1) {
        s0 += __shfl_xor_sync(0xffffffffu, s0, o);
        s1 += __shfl_xor_sync(0xffffffffu, s1, o);
    }
    if (lane == 0) { lg[2 * warp] = s0; lg[2 * warp + 1] = s1; }
    __syncthreads();
    if (tid == 0) {
        int b0 = 0;
        float v0 = lg[0];
        for (int e = 1; e < NE; e++)
            if (lg[e] > v0) { v0 = lg[e]; b0 = e; }
        int b1 = -1;
        float v1 = -3e38f;
        for (int e = 0; e < NE; e++)
            if (e != b0 && lg[e] > v1) { v1 = lg[e]; b1 = e; }
        float w0 = 1.f / (1.f + __expf(v1 - v0));
        g_eid[2 * t] = b0;
        g_eid[2 * t + 1] = b1;
        g_ew[2 * t] = w0;
        g_ew[2 * t + 1] = 1.f - w0;
        atomicAdd(&g_cnt[b0], 1);
        atomicAdd(&g_cnt[b1], 1);
    }
}

// ---------------------------------------------------------------------------
// Routing plumbing
// ---------------------------------------------------------------------------
__global__ void k_reset(void) {
    if (threadIdx.x < NE) {
        g_cnt[threadIdx.x] = 0;
        g_cur[threadIdx.x] = 0;
    }
}

__global__ void k_scan(void) {
    if (threadIdx.x == 0) {
        int a = 0;
        for (int e = 0; e < NE; e++) {
            g_off[e] = a;
            a += g_cnt[e];
        }
        g_off[NE] = a;
    }
}

__global__ void k_scatter(void) {
    int t = blockIdx.x * blockDim.x + threadIdx.x;
    if (t >= SEQ) return;
#pragma unroll
    for (int slot = 0; slot < 2; slot++) {
        int e = g_eid[2 * t + slot];
        int pos = g_off[e] + atomicAdd(&g_cur[e], 1);
        g_ptok[pos] = t;
        g_tslot[2 * t + slot] = pos;
    }
}

__global__ void k_combine(float* __restrict__ out) {
    int t = blockIdx.x;
    int i = threadIdx.x;
    int p0 = g_tslot[2 * t], p1 = g_tslot[2 * t + 1];
    float w0 = g_ew[2 * t], w1 = g_ew[2 * t + 1];
    float4 a = reinterpret_cast<const float4*>(g_h1 + (size_t)t * HID)[i];
    float4 b = reinterpret_cast<const float4*>(g_Dn + (size_t)p0 * HID)[i];
    float4 c = reinterpret_cast<const float4*>(g_Dn + (size_t)p1 * HID)[i];
    float4 o = make_float4(a.x + w0 * b.x + w1 * c.x,
                           a.y + w0 * b.y + w1 * c.y,
                           a.z + w0 * b.z + w1 * c.z,
                           a.w + w0 * b.w + w1 * c.w);
    reinterpret_cast<float4*>(out + (size_t)t * HID)[i] = o;
}

// ---------------------------------------------------------------------------
// Launch
// ---------------------------------------------------------------------------
extern "C" void kernel_launch(void* const* d_in, const int* in_sizes, int n_in,
                              void* d_out, int out_size) {
    (void)in_sizes; (void)n_in; (void)out_size;
    const float* x        = (const float*)d_in[0];
    const float* norm1_w  = (const float*)d_in[1];
    const float* w_qkv    = (const float*)d_in[2];
    const float* w_out    = (const float*)d_in[3];
    const float* norm2_w  = (const float*)d_in[4];
    const float* w_router = (const float*)d_in[5];
    const float* w_gateup = (const float*)d_in[6];
    const float* w_down   = (const float*)d_in[7];
    float* out = (float*)d_out;

    cudaFuncSetAttribute(k_attn, cudaFuncAttributeMaxDynamicSharedMemorySize,
                         ATT_SMEM_BYTES);
    cudaFuncSetAttribute(k_gemm_qkv, cudaFuncAttributeMaxDynamicSharedMemorySize,
                         SMEM_SINGLE_B);
    cudaFuncSetAttribute(k_gemm_out, cudaFuncAttributeMaxDynamicSharedMemorySize,
                         SMEM_DUAL_B);
    cudaFuncSetAttribute(k_moe_gemm1, cudaFuncAttributeMaxDynamicSharedMemorySize,
                         SMEM_DUAL_B);
    cudaFuncSetAttribute(k_moe_gemm2, cudaFuncAttributeMaxDynamicSharedMemorySize,
                         SMEM_DUAL_B);

    k_reset<<<1, 32>>>();
    k_rmsnorm1<<<SEQ, 256>>>(x, norm1_w);
    k_gemm_qkv<<<dim3(SEQ / 128, QKVC / 128), 256, SMEM_SINGLE_B>>>(w_qkv);
    k_attn<<<dim3(SEQ / 64, NQ), 256, ATT_SMEM_BYTES>>>();
    k_gemm_out<<<dim3(SEQ / 128, HID / 256), 256, SMEM_DUAL_B>>>(w_out, x);
    k_rms2router<<<SEQ, 256>>>(norm2_w, w_router);
    k_scan<<<1, 32>>>();
    k_scatter<<<(SEQ + 255) / 256, 256>>>();
    k_moe_gemm1<<<dim3(NE * 16, FF / 128), 256, SMEM_DUAL_B>>>(w_gateup);
    k_moe_gemm2<<<dim3(NE * 16, HID / 256), 256, SMEM_DUAL_B>>>(w_down);
    k_combine<<<SEQ, 192>>>(out);
}

// round 9
// speedup vs baseline: 1.6951x; 1.6951x over previous
#include <cuda_runtime.h>
#include <math.h>

// ---------------------------------------------------------------------------
// Constants
// ---------------------------------------------------------------------------
#define SEQ   2048
#define HID   768
#define NQ    12
#define NKV   3
#define HD    64
#define QKVC  1152
#define NE    16
#define FF    1536
#define SLOTS 4096

// GEMM smem geometry (3-stage pipeline)
#define SA_STRIDE 20
#define SB_STRIDE 136          // 8c+8ni+g -> conflict-free B frags
#define SA_STAGE  (128 * SA_STRIDE)
#define SB_STAGE  (16 * SB_STRIDE)
#define SMEM_SINGLE_B ((3 * SA_STAGE + 3 * SB_STAGE) * 4)
#define SMEM_DUAL_B   ((3 * SA_STAGE + 6 * SB_STAGE) * 4)

// ---------------------------------------------------------------------------
// Device scratch
// ---------------------------------------------------------------------------
__device__ float g_xn1[SEQ * HID];
__device__ float g_Q[NQ * SEQ * HD];
__device__ float g_K[NKV * SEQ * HD];
__device__ float g_V[NKV * SEQ * HD];
__device__ float g_attn[SEQ * HID];
__device__ float g_h1[SEQ * HID];
__device__ float g_xn2[SEQ * HID];
__device__ float g_cos[SEQ * 32];
__device__ float g_sin[SEQ * 32];
__device__ int   g_eid[SLOTS];
__device__ float g_ew[SLOTS];
__device__ int   g_cnt[NE];
__device__ int   g_off[NE + 1];
__device__ int   g_cur[NE];
__device__ int   g_ptok[SLOTS];
__device__ int   g_tslot[SLOTS];
__device__ float g_Hact[(size_t)SLOTS * FF];
__device__ float g_Dn[(size_t)SLOTS * HID];

// ---------------------------------------------------------------------------
// Helpers
// ---------------------------------------------------------------------------
__device__ __forceinline__ void mma_tf32(float d[4], const unsigned a[4],
                                         const unsigned b[2]) {
    asm volatile(
        "mma.sync.aligned.m16n8k8.row.col.f32.tf32.tf32.f32 "
        "{%0,%1,%2,%3}, {%4,%5,%6,%7}, {%8,%9}, {%0,%1,%2,%3};"
        : "+f"(d[0]), "+f"(d[1]), "+f"(d[2]), "+f"(d[3])
        : "r"(a[0]), "r"(a[1]), "r"(a[2]), "r"(a[3]),
          "r"(b[0]), "r"(b[1]));
}

__device__ __forceinline__ void cp16(void* smem_dst, const void* gmem_src, bool pred) {
    unsigned d = (unsigned)__cvta_generic_to_shared(smem_dst);
    int sz = pred ? 16 : 0;
    asm volatile("cp.async.cg.shared.global [%0], [%1], 16, %2;"
                 :: "r"(d), "l"(gmem_src), "r"(sz) : "memory");
}

// ---------------------------------------------------------------------------
// RoPE table: accurate sincosf once, table-lookup everywhere else
// ---------------------------------------------------------------------------
__global__ void k_ropetab(void) {
    int idx = blockIdx.x * blockDim.x + threadIdx.x;   // SEQ*32
    int s = idx >> 5, i = idx & 31;
    float inv = powf(10000.f, -(float)(2 * i) / 64.f);
    float sn, cs;
    sincosf((float)s * inv, &sn, &cs);
    g_cos[idx] = cs;
    g_sin[idx] = sn;
}

// ---------------------------------------------------------------------------
// RMSNorm 1
// ---------------------------------------------------------------------------
__global__ void k_rmsnorm1(const float* __restrict__ x, const float* __restrict__ w) {
    int row = blockIdx.x;
    const float* xr = x + (size_t)row * HID;
    float s = 0.f;
    for (int i = threadIdx.x; i < HID; i += 256) {
        float v = xr[i];
        s += v * v;
    }
    __shared__ float red[256];
    red[threadIdx.x] = s;
    __syncthreads();
    for (int o = 128; o > 0; o >>= 1) {
        if (threadIdx.x < o) red[threadIdx.x] += red[threadIdx.x + o];
        __syncthreads();
    }
    float scale = rsqrtf(red[0] / (float)HID + 1e-6f);
    for (int i = threadIdx.x; i < HID; i += 256)
        g_xn1[(size_t)row * HID + i] = xr[i] * scale * w[i];
}

// ---------------------------------------------------------------------------
// Single-B TF32 GEMM core (3-stage cp.async)
// ---------------------------------------------------------------------------
__device__ __forceinline__ void gemm_single3(
    const float* Ar0, const float* Ar1, bool p0, bool p1,
    const float* Br0, const float* Br1, int ldb,
    int K, unsigned* SA, unsigned* SB, float acc[4][4][4])
{
    int tid = threadIdx.x;
    int warp = tid >> 5, lane = tid & 31;
    int wm = warp >> 2, wn = warp & 3;
    int g = lane >> 2, c = lane & 3;
    int ar0 = tid >> 2, ar1 = ar0 + 64;
    int akq = (tid & 3) * 4;
    int bkr0 = tid >> 5, bkr1 = bkr0 + 8;
    int bc4 = (tid & 31) * 4;

#define ST1(s, k0)                                                            \
    do {                                                                      \
        unsigned* a_ = SA + (s) * SA_STAGE;                                   \
        unsigned* b_ = SB + (s) * SB_STAGE;                                   \
        cp16(a_ + ar0 * SA_STRIDE + akq, Ar0 + (k0), p0);                     \
        cp16(a_ + ar1 * SA_STRIDE + akq, Ar1 + (k0), p1);                     \
        cp16(b_ + bkr0 * SB_STRIDE + bc4, Br0 + (size_t)(k0) * ldb, true);    \
        cp16(b_ + bkr1 * SB_STRIDE + bc4, Br1 + (size_t)(k0) * ldb, true);    \
        asm volatile("cp.async.commit_group;" ::: "memory");                  \
    } while (0)

    ST1(0, 0);
    ST1(1, 16);
    int buf = 0;
    for (int k0 = 0; k0 < K; k0 += 16) {
        if (k0 + 32 < K) {
            asm volatile("cp.async.wait_group 1;" ::: "memory");
            __syncthreads();
            ST1(buf == 0 ? 2 : buf - 1, k0 + 32);
        } else {
            asm volatile("cp.async.wait_group 0;" ::: "memory");
            __syncthreads();
        }
        unsigned* a_ = SA + buf * SA_STAGE;
        unsigned* b_ = SB + buf * SB_STAGE;
#pragma unroll
        for (int kk = 0; kk < 16; kk += 8) {
            unsigned af[4][4];
#pragma unroll
            for (int mi = 0; mi < 4; mi++) {
                int m = wm * 64 + mi * 16;
                af[mi][0] = a_[(m + g) * SA_STRIDE + kk + c];
                af[mi][1] = a_[(m + g + 8) * SA_STRIDE + kk + c];
                af[mi][2] = a_[(m + g) * SA_STRIDE + kk + c + 4];
                af[mi][3] = a_[(m + g + 8) * SA_STRIDE + kk + c + 4];
            }
#pragma unroll
            for (int ni = 0; ni < 4; ni++) {
                int n = wn * 32 + ni * 8 + g;
                unsigned bf[2];
                bf[0] = b_[(kk + c) * SB_STRIDE + n];
                bf[1] = b_[(kk + c + 4) * SB_STRIDE + n];
#pragma unroll
                for (int mi = 0; mi < 4; mi++)
                    mma_tf32(acc[mi][ni], af[mi], bf);
            }
        }
        buf = (buf == 2) ? 0 : buf + 1;
    }
#undef ST1
}

// ---------------------------------------------------------------------------
// Dual-B TF32 GEMM core
// ---------------------------------------------------------------------------
__device__ __forceinline__ void gemm_dual3(
    const float* Ar0, const float* Ar1, bool p0, bool p1,
    const float* B0r0, const float* B0r1,
    const float* B1r0, const float* B1r1, int ldb,
    int K, unsigned* SA, unsigned* SB0, unsigned* SB1,
    float accg[4][4][4], float accu[4][4][4])
{
    int tid = threadIdx.x;
    int warp = tid >> 5, lane = tid & 31;
    int wm = warp >> 2, wn = warp & 3;
    int g = lane >> 2, c = lane & 3;
    int ar0 = tid >> 2, ar1 = ar0 + 64;
    int akq = (tid & 3) * 4;
    int bkr0 = tid >> 5, bkr1 = bkr0 + 8;
    int bc4 = (tid & 31) * 4;

#define STD(s, k0)                                                            \
    do {                                                                      \
        unsigned* a_  = SA + (s) * SA_STAGE;                                  \
        unsigned* b0_ = SB0 + (s) * SB_STAGE;                                 \
        unsigned* b1_ = SB1 + (s) * SB_STAGE;                                 \
        cp16(a_ + ar0 * SA_STRIDE + akq, Ar0 + (k0), p0);                     \
        cp16(a_ + ar1 * SA_STRIDE + akq, Ar1 + (k0), p1);                     \
        cp16(b0_ + bkr0 * SB_STRIDE + bc4, B0r0 + (size_t)(k0) * ldb, true);  \
        cp16(b0_ + bkr1 * SB_STRIDE + bc4, B0r1 + (size_t)(k0) * ldb, true);  \
        cp16(b1_ + bkr0 * SB_STRIDE + bc4, B1r0 + (size_t)(k0) * ldb, true);  \
        cp16(b1_ + bkr1 * SB_STRIDE + bc4, B1r1 + (size_t)(k0) * ldb, true);  \
        asm volatile("cp.async.commit_group;" ::: "memory");                  \
    } while (0)

    STD(0, 0);
    STD(1, 16);
    int buf = 0;
    for (int k0 = 0; k0 < K; k0 += 16) {
        if (k0 + 32 < K) {
            asm volatile("cp.async.wait_group 1;" ::: "memory");
            __syncthreads();
            STD(buf == 0 ? 2 : buf - 1, k0 + 32);
        } else {
            asm volatile("cp.async.wait_group 0;" ::: "memory");
            __syncthreads();
        }
        unsigned* a_  = SA + buf * SA_STAGE;
        unsigned* b0_ = SB0 + buf * SB_STAGE;
        unsigned* b1_ = SB1 + buf * SB_STAGE;
#pragma unroll
        for (int kk = 0; kk < 16; kk += 8) {
            unsigned af[4][4];
#pragma unroll
            for (int mi = 0; mi < 4; mi++) {
                int m = wm * 64 + mi * 16;
                af[mi][0] = a_[(m + g) * SA_STRIDE + kk + c];
                af[mi][1] = a_[(m + g + 8) * SA_STRIDE + kk + c];
                af[mi][2] = a_[(m + g) * SA_STRIDE + kk + c + 4];
                af[mi][3] = a_[(m + g + 8) * SA_STRIDE + kk + c + 4];
            }
#pragma unroll
            for (int ni = 0; ni < 4; ni++) {
                int n = wn * 32 + ni * 8 + g;
                unsigned bf0[2], bf1[2];
                bf0[0] = b0_[(kk + c) * SB_STRIDE + n];
                bf0[1] = b0_[(kk + c + 4) * SB_STRIDE + n];
                bf1[0] = b1_[(kk + c) * SB_STRIDE + n];
                bf1[1] = b1_[(kk + c + 4) * SB_STRIDE + n];
#pragma unroll
                for (int mi = 0; mi < 4; mi++) {
                    mma_tf32(accg[mi][ni], af[mi], bf0);
                    mma_tf32(accu[mi][ni], af[mi], bf1);
                }
            }
        }
        buf = (buf == 2) ? 0 : buf + 1;
    }
#undef STD
}

// ---------------------------------------------------------------------------
// QKV projection + fused RoPE epilogue (table-based) -> g_Q / g_K / g_V
// ---------------------------------------------------------------------------
__global__ void __launch_bounds__(256) k_gemm_qkv(const float* __restrict__ W) {
    extern __shared__ unsigned dsm[];
    int mb = blockIdx.x, nb = blockIdx.y;
    int tid = threadIdx.x;
    float acc[4][4][4] = {};
    {
        int ar0 = tid >> 2, ar1 = ar0 + 64;
        int akq = (tid & 3) * 4;
        int bkr0 = tid >> 5, bkr1 = bkr0 + 8;
        int bc4 = (tid & 31) * 4;
        const float* A = g_xn1 + (size_t)mb * 128 * HID;
        const float* B = W + nb * 128;
        gemm_single3(A + (size_t)ar0 * HID + akq, A + (size_t)ar1 * HID + akq,
                     true, true,
                     B + (size_t)bkr0 * QKVC + bc4, B + (size_t)bkr1 * QKVC + bc4,
                     QKVC, HID, dsm, dsm + 3 * SA_STAGE, acc);
    }
    int warp = tid >> 5, lane = tid & 31;
    int wm = warp >> 2, wn = warp & 3, g = lane >> 2, c = lane & 3;
#pragma unroll
    for (int mi = 0; mi < 4; mi++) {
#pragma unroll
        for (int ni = 0; ni < 4; ni++) {
            int r   = mb * 128 + wm * 64 + mi * 16 + g;
            int col = nb * 128 + wn * 32 + ni * 8 + 2 * c;
            int dm  = col & 63;
            int pi  = dm >> 1;
            float a0 = acc[mi][ni][0], a1 = acc[mi][ni][1];
            float b0 = acc[mi][ni][2], b1 = acc[mi][ni][3];
            if (col < NQ * HD) {
                int hh = col >> 6;
                float cs0 = g_cos[r * 32 + pi],       sn0 = g_sin[r * 32 + pi];
                float cs1 = g_cos[(r + 8) * 32 + pi], sn1 = g_sin[(r + 8) * 32 + pi];
                float* d0 = g_Q + ((size_t)hh * SEQ + r) * HD + dm;
                float* d1 = g_Q + ((size_t)hh * SEQ + r + 8) * HD + dm;
                *reinterpret_cast<float2*>(d0) = make_float2(a0 * cs0 - a1 * sn0, a0 * sn0 + a1 * cs0);
                *reinterpret_cast<float2*>(d1) = make_float2(b0 * cs1 - b1 * sn1, b0 * sn1 + b1 * cs1);
            } else if (col < (NQ + NKV) * HD) {
                int hh = (col - NQ * HD) >> 6;
                float cs0 = g_cos[r * 32 + pi],       sn0 = g_sin[r * 32 + pi];
                float cs1 = g_cos[(r + 8) * 32 + pi], sn1 = g_sin[(r + 8) * 32 + pi];
                float* d0 = g_K + ((size_t)hh * SEQ + r) * HD + dm;
                float* d1 = g_K + ((size_t)hh * SEQ + r + 8) * HD + dm;
                *reinterpret_cast<float2*>(d0) = make_float2(a0 * cs0 - a1 * sn0, a0 * sn0 + a1 * cs0);
                *reinterpret_cast<float2*>(d1) = make_float2(b0 * cs1 - b1 * sn1, b0 * sn1 + b1 * cs1);
            } else {
                int hh = (col - (NQ + NKV) * HD) >> 6;
                float* d0 = g_V + ((size_t)hh * SEQ + r) * HD + dm;
                float* d1 = g_V + ((size_t)hh * SEQ + r + 8) * HD + dm;
                *reinterpret_cast<float2*>(d0) = make_float2(a0, a1);
                *reinterpret_cast<float2*>(d1) = make_float2(b0, b1);
            }
        }
    }
}

// ---------------------------------------------------------------------------
// Out projection + residual (dual-B): g_h1 = x + g_attn @ w_out
// ---------------------------------------------------------------------------
__global__ void __launch_bounds__(256) k_gemm_out(const float* __restrict__ W,
                                                  const float* __restrict__ xres) {
    extern __shared__ unsigned dsm[];
    int mb = blockIdx.x, nb = blockIdx.y;
    int tid = threadIdx.x;
    float accg[4][4][4] = {};
    float accu[4][4][4] = {};
    {
        int ar0 = tid >> 2, ar1 = ar0 + 64;
        int akq = (tid & 3) * 4;
        int bkr0 = tid >> 5, bkr1 = bkr0 + 8;
        int bc4 = (tid & 31) * 4;
        const float* A  = g_attn + (size_t)mb * 128 * HID;
        const float* B0 = W + nb * 128;
        const float* B1 = B0 + 384;
        gemm_dual3(A + (size_t)ar0 * HID + akq, A + (size_t)ar1 * HID + akq, true, true,
                   B0 + (size_t)bkr0 * HID + bc4, B0 + (size_t)bkr1 * HID + bc4,
                   B1 + (size_t)bkr0 * HID + bc4, B1 + (size_t)bkr1 * HID + bc4,
                   HID, HID, dsm, dsm + 3 * SA_STAGE, dsm + 3 * SA_STAGE + 3 * SB_STAGE,
                   accg, accu);
    }
    int warp = tid >> 5, lane = tid & 31;
    int wm = warp >> 2, wn = warp & 3, g = lane >> 2, c = lane & 3;
#pragma unroll
    for (int mi = 0; mi < 4; mi++) {
#pragma unroll
        for (int ni = 0; ni < 4; ni++) {
            int r = mb * 128 + wm * 64 + mi * 16 + g;
            int col0 = nb * 128 + wn * 32 + ni * 8 + 2 * c;
#pragma unroll
            for (int half = 0; half < 2; half++) {
                float* ac = half ? accu[mi][ni] : accg[mi][ni];
                int col = col0 + half * 384;
                size_t o0 = (size_t)r * HID + col;
                size_t o1 = (size_t)(r + 8) * HID + col;
                float2 x0 = *reinterpret_cast<const float2*>(xres + o0);
                float2 x1 = *reinterpret_cast<const float2*>(xres + o1);
                *reinterpret_cast<float2*>(g_h1 + o0) = make_float2(x0.x + ac[0], x0.y + ac[1]);
                *reinterpret_cast<float2*>(g_h1 + o1) = make_float2(x1.x + ac[2], x1.y + ac[3]);
            }
        }
    }
}

// ---------------------------------------------------------------------------
// MoE GEMM1 (indirect A rows via ptok) fused with SiLU*up -> g_Hact
// ---------------------------------------------------------------------------
__global__ void __launch_bounds__(256) k_moe_gemm1(const float* __restrict__ Wgu) {
    extern __shared__ unsigned dsm[];
    __shared__ int sptok[128];
    int e = blockIdx.x >> 4, mb = blockIdx.x & 15, nb = blockIdx.y;
    int r0 = g_off[e];
    int rows_e = g_off[e + 1] - r0;
    int rbase = mb * 128;
    if (rbase >= rows_e) return;
    int rows = min(128, rows_e - rbase);
    int tid = threadIdx.x;
    if (tid < 128) sptok[tid] = (tid < rows) ? g_ptok[r0 + rbase + tid] : 0;
    __syncthreads();

    float accg[4][4][4] = {};
    float accu[4][4][4] = {};
    {
        int ar0 = tid >> 2, ar1 = ar0 + 64;
        int akq = (tid & 3) * 4;
        int bkr0 = tid >> 5, bkr1 = bkr0 + 8;
        int bc4 = (tid & 31) * 4;
        bool p0 = ar0 < rows, p1 = ar1 < rows;
        const float* Ar0 = g_xn2 + (size_t)sptok[ar0] * HID + akq;
        const float* Ar1 = g_xn2 + (size_t)sptok[ar1] * HID + akq;
        const float* Bg = Wgu + (size_t)e * HID * (2 * FF) + nb * 128;
        const float* Bu = Bg + FF;
        gemm_dual3(Ar0, Ar1, p0, p1,
                   Bg + (size_t)bkr0 * (2 * FF) + bc4, Bg + (size_t)bkr1 * (2 * FF) + bc4,
                   Bu + (size_t)bkr0 * (2 * FF) + bc4, Bu + (size_t)bkr1 * (2 * FF) + bc4,
                   2 * FF, HID, dsm, dsm + 3 * SA_STAGE, dsm + 3 * SA_STAGE + 3 * SB_STAGE,
                   accg, accu);
    }
    int warp = tid >> 5, lane = tid & 31;
    int wm = warp >> 2, wn = warp & 3, g = lane >> 2, c = lane & 3;
    float* Cp = g_Hact + (size_t)(r0 + rbase) * FF + nb * 128;
#pragma unroll
    for (int mi = 0; mi < 4; mi++) {
#pragma unroll
        for (int ni = 0; ni < 4; ni++) {
            int rr = wm * 64 + mi * 16 + g;
            int col = wn * 32 + ni * 8 + 2 * c;
            float h[4];
#pragma unroll
            for (int j = 0; j < 4; j++) {
                float gv = accg[mi][ni][j];
                h[j] = gv / (1.f + __expf(-gv)) * accu[mi][ni][j];
            }
            if (rr < rows)
                *reinterpret_cast<float2*>(Cp + (size_t)rr * FF + col) =
                    make_float2(h[0], h[1]);
            if (rr + 8 < rows)
                *reinterpret_cast<float2*>(Cp + (size_t)(rr + 8) * FF + col) =
                    make_float2(h[2], h[3]);
        }
    }
}

// ---------------------------------------------------------------------------
// MoE GEMM2 (dual-B): Dn[slot] = Hact[slot] @ w_down[e]
// ---------------------------------------------------------------------------
__global__ void __launch_bounds__(256) k_moe_gemm2(const float* __restrict__ Wd) {
    extern __shared__ unsigned dsm[];
    int e = blockIdx.x >> 4, mb = blockIdx.x & 15, nb = blockIdx.y;
    int r0 = g_off[e];
    int rows_e = g_off[e + 1] - r0;
    int rbase = mb * 128;
    if (rbase >= rows_e) return;
    int rows = min(128, rows_e - rbase);
    int tid = threadIdx.x;
    float accg[4][4][4] = {};
    float accu[4][4][4] = {};
    {
        int ar0 = tid >> 2, ar1 = ar0 + 64;
        int akq = (tid & 3) * 4;
        int bkr0 = tid >> 5, bkr1 = bkr0 + 8;
        int bc4 = (tid & 31) * 4;
        bool p0 = ar0 < rows, p1 = ar1 < rows;
        const float* A = g_Hact + (size_t)(r0 + rbase) * FF;
        const float* Ar0 = A + (size_t)(p0 ? ar0 : 0) * FF + akq;
        const float* Ar1 = A + (size_t)(p1 ? ar1 : 0) * FF + akq;
        const float* B0 = Wd + (size_t)e * FF * HID + nb * 128;
        const float* B1 = B0 + 384;
        gemm_dual3(Ar0, Ar1, p0, p1,
                   B0 + (size_t)bkr0 * HID + bc4, B0 + (size_t)bkr1 * HID + bc4,
                   B1 + (size_t)bkr0 * HID + bc4, B1 + (size_t)bkr1 * HID + bc4,
                   HID, FF, dsm, dsm + 3 * SA_STAGE, dsm + 3 * SA_STAGE + 3 * SB_STAGE,
                   accg, accu);
    }
    int warp = tid >> 5, lane = tid & 31;
    int wm = warp >> 2, wn = warp & 3, g = lane >> 2, c = lane & 3;
    float* Cp = g_Dn + (size_t)(r0 + rbase) * HID + nb * 128;
#pragma unroll
    for (int mi = 0; mi < 4; mi++) {
#pragma unroll
        for (int ni = 0; ni < 4; ni++) {
            int rr = wm * 64 + mi * 16 + g;
            int col0 = wn * 32 + ni * 8 + 2 * c;
#pragma unroll
            for (int half = 0; half < 2; half++) {
                float* ac = half ? accu[mi][ni] : accg[mi][ni];
                int col = col0 + half * 384;
                if (rr < rows)
                    *reinterpret_cast<float2*>(Cp + (size_t)rr * HID + col) =
                        make_float2(ac[0], ac[1]);
                if (rr + 8 < rows)
                    *reinterpret_cast<float2*>(Cp + (size_t)(rr + 8) * HID + col) =
                        make_float2(ac[2], ac[3]);
            }
        }
    }
}

// ---------------------------------------------------------------------------
// Flash attention, TF32 tensor cores, cp.async double-buffered K/V.
// P aliases the S buffer (same index read->write per thread, stride 68).
// smem: Q,K0,K1,SP @68 + V0,V1 @72 + scalars = 107 KB -> 2 CTAs/SM.
// ---------------------------------------------------------------------------
#define ATT_W (4 * (64 * 68) + 2 * (64 * 72) + 3 * 64)
#define ATT_SMEM_BYTES (ATT_W * 4)

__global__ void k_attn(void) {
    extern __shared__ unsigned smu[];
    unsigned* uQ  = smu;                    // [64][68]
    unsigned* uK0 = uQ + 64 * 68;           // [64][68]
    unsigned* uK1 = uK0 + 64 * 68;
    unsigned* uSP = uK1 + 64 * 68;          // [64][68]  S (float bits) then P
    unsigned* uV0 = uSP + 64 * 68;          // [64][72]
    unsigned* uV1 = uV0 + 64 * 72;
    float* mrow  = (float*)(uV1 + 64 * 72);
    float* lrow  = mrow + 64;
    float* arow  = lrow + 64;

    int qb = gridDim.x - 1 - blockIdx.x;
    int h  = blockIdx.y;
    int kvh = h >> 2;
    int tid = threadIdx.x;
    int warp = tid >> 5, lane = tid & 31;
    int wm = warp >> 2, wn = warp & 3;
    int g  = lane >> 2, c = lane & 3;

    const float* Kbase = g_K + (size_t)kvh * SEQ * HD;
    const float* Vbase = g_V + (size_t)kvh * SEQ * HD;

#define ATT_ISSUE(buf_, kb_)                                                  \
    do {                                                                      \
        unsigned* dK = (buf_) ? uK1 : uK0;                                    \
        unsigned* dV = (buf_) ? uV1 : uV0;                                    \
        const float* Kb_ = Kbase + (size_t)(kb_) * 64 * HD;                   \
        const float* Vb_ = Vbase + (size_t)(kb_) * 64 * HD;                   \
        _Pragma("unroll")                                                     \
        for (int it = 0; it < 4; it++) {                                      \
            int e_ = tid + it * 256;                                          \
            int r_ = e_ >> 4;                                                 \
            int q_ = (e_ & 15) * 4;                                           \
            cp16(dK + r_ * 68 + q_, Kb_ + r_ * HD + q_, true);                \
            cp16(dV + r_ * 72 + q_, Vb_ + r_ * HD + q_, true);                \
        }                                                                     \
        asm volatile("cp.async.commit_group;" ::: "memory");                  \
    } while (0)

    ATT_ISSUE(0, 0);
    if (qb > 0) ATT_ISSUE(1, 1);

    const float* Qb = g_Q + ((size_t)h * SEQ + qb * 64) * HD;
    for (int e = tid; e < 4096; e += 256) {
        int r = e >> 6, d = e & 63;
        uQ[r * 68 + d] = __float_as_uint(Qb[r * HD + d] * 0.125f);
    }
    if (tid < 64) { mrow[tid] = -1e30f; lrow[tid] = 0.f; }

    float oacc[2][2][4] = {};
    for (int kb = 0; kb <= qb; kb++) {
        int buf = kb & 1;
        if (kb < qb)
            asm volatile("cp.async.wait_group 1;" ::: "memory");
        else
            asm volatile("cp.async.wait_group 0;" ::: "memory");
        __syncthreads();
        unsigned* cK = buf ? uK1 : uK0;
        unsigned* cV = buf ? uV1 : uV0;

        // ---- S = Q @ K^T ----
        float sacc[2][2][4] = {};
#pragma unroll
        for (int kk = 0; kk < 64; kk += 8) {
            unsigned af[2][4];
#pragma unroll
            for (int mi = 0; mi < 2; mi++) {
                int m = wm * 32 + mi * 16;
                af[mi][0] = uQ[(m + g) * 68 + kk + c];
                af[mi][1] = uQ[(m + g + 8) * 68 + kk + c];
                af[mi][2] = uQ[(m + g) * 68 + kk + c + 4];
                af[mi][3] = uQ[(m + g + 8) * 68 + kk + c + 4];
            }
#pragma unroll
            for (int ni = 0; ni < 2; ni++) {
                int n = wn * 16 + ni * 8 + g;
                unsigned bf[2];
                bf[0] = cK[n * 68 + kk + c];
                bf[1] = cK[n * 68 + kk + c + 4];
#pragma unroll
                for (int mi = 0; mi < 2; mi++)
                    mma_tf32(sacc[mi][ni], af[mi], bf);
            }
        }
        bool diag = (kb == qb);
#pragma unroll
        for (int mi = 0; mi < 2; mi++) {
#pragma unroll
            for (int ni = 0; ni < 2; ni++) {
                int r0 = wm * 32 + mi * 16 + g;
                int cl = wn * 16 + ni * 8 + 2 * c;
                float v0 = sacc[mi][ni][0], v1 = sacc[mi][ni][1];
                float v2 = sacc[mi][ni][2], v3 = sacc[mi][ni][3];
                if (diag) {
                    if (cl > r0)     v0 = -1e30f;
                    if (cl + 1 > r0) v1 = -1e30f;
                    if (cl > r0 + 8)     v2 = -1e30f;
                    if (cl + 1 > r0 + 8) v3 = -1e30f;
                }
                uSP[r0 * 68 + cl]           = __float_as_uint(v0);
                uSP[r0 * 68 + cl + 1]       = __float_as_uint(v1);
                uSP[(r0 + 8) * 68 + cl]     = __float_as_uint(v2);
                uSP[(r0 + 8) * 68 + cl + 1] = __float_as_uint(v3);
            }
        }
        __syncthreads();

        // ---- online softmax (4 lanes/row), P written in place over S ----
        {
            int i  = tid >> 2;
            int jq = (tid & 3) * 16;
            float sv[16];
            float mx = -1e30f;
#pragma unroll
            for (int j = 0; j < 16; j++) {
                sv[j] = __uint_as_float(uSP[i * 68 + jq + j]);
                mx = fmaxf(mx, sv[j]);
            }
            mx = fmaxf(mx, __shfl_xor_sync(0xffffffffu, mx, 1));
            mx = fmaxf(mx, __shfl_xor_sync(0xffffffffu, mx, 2));
            float mold = mrow[i];
            mx = fmaxf(mx, mold);
            float sum = 0.f;
#pragma unroll
            for (int j = 0; j < 16; j++) {
                float p = __expf(sv[j] - mx);
                uSP[i * 68 + jq + j] = __float_as_uint(p);
                sum += p;
            }
            sum += __shfl_xor_sync(0xffffffffu, sum, 1);
            sum += __shfl_xor_sync(0xffffffffu, sum, 2);
            if ((tid & 3) == 0) {
                float al = __expf(mold - mx);
                lrow[i] = lrow[i] * al + sum;
                mrow[i] = mx;
                arow[i] = al;
            }
        }
        __syncthreads();

        // ---- rescale + O += P @ V ----
#pragma unroll
        for (int mi = 0; mi < 2; mi++) {
            float a0 = arow[wm * 32 + mi * 16 + g];
            float a1 = arow[wm * 32 + mi * 16 + g + 8];
#pragma unroll
            for (int ni = 0; ni < 2; ni++) {
                oacc[mi][ni][0] *= a0;
                oacc[mi][ni][1] *= a0;
                oacc[mi][ni][2] *= a1;
                oacc[mi][ni][3] *= a1;
            }
        }
#pragma unroll
        for (int kk = 0; kk < 64; kk += 8) {
            unsigned af[2][4];
#pragma unroll
            for (int mi = 0; mi < 2; mi++) {
                int m = wm * 32 + mi * 16;
                af[mi][0] = uSP[(m + g) * 68 + kk + c];
                af[mi][1] = uSP[(m + g + 8) * 68 + kk + c];
                af[mi][2] = uSP[(m + g) * 68 + kk + c + 4];
                af[mi][3] = uSP[(m + g + 8) * 68 + kk + c + 4];
            }
#pragma unroll
            for (int ni = 0; ni < 2; ni++) {
                int n = wn * 16 + ni * 8 + g;
                unsigned bf[2];
                bf[0] = cV[(kk + c) * 72 + n];
                bf[1] = cV[(kk + c + 4) * 72 + n];
#pragma unroll
                for (int mi = 0; mi < 2; mi++)
                    mma_tf32(oacc[mi][ni], af[mi], bf);
            }
        }
        // prefetch kb+2 into this buffer (its readers are done)
        if (kb + 2 <= qb) {
            __syncthreads();
            ATT_ISSUE(buf, kb + 2);
        }
    }

    __syncthreads();
#pragma unroll
    for (int mi = 0; mi < 2; mi++) {
        int rl0 = wm * 32 + mi * 16 + g;
        float i0 = 1.f / lrow[rl0];
        float i1 = 1.f / lrow[rl0 + 8];
        int gr0 = qb * 64 + rl0;
#pragma unroll
        for (int ni = 0; ni < 2; ni++) {
            int col = h * HD + wn * 16 + ni * 8 + 2 * c;
            *reinterpret_cast<float2*>(g_attn + (size_t)gr0 * HID + col) =
                make_float2(oacc[mi][ni][0] * i0, oacc[mi][ni][1] * i0);
            *reinterpret_cast<float2*>(g_attn + (size_t)(gr0 + 8) * HID + col) =
                make_float2(oacc[mi][ni][2] * i1, oacc[mi][ni][3] * i1);
        }
    }
#undef ATT_ISSUE
}

// ---------------------------------------------------------------------------
// Fused RMSNorm2 + router (fp32)
// ---------------------------------------------------------------------------
__global__ void k_rms2router(const float* __restrict__ w, const float* __restrict__ Wr) {
    int t = blockIdx.x;
    int tid = threadIdx.x;
    __shared__ float sxn[HID];
    __shared__ float red[256];
    __shared__ float lg[NE];
    const float* xr = g_h1 + (size_t)t * HID;
    float s = 0.f;
    for (int i = tid; i < HID; i += 256) {
        float v = xr[i];
        s += v * v;
    }
    red[tid] = s;
    __syncthreads();
    for (int o = 128; o > 0; o >>= 1) {
        if (tid < o) red[tid] += red[tid + o];
        __syncthreads();
    }
    float scale = rsqrtf(red[0] / (float)HID + 1e-6f);
    for (int i = tid; i < HID; i += 256) {
        float v = xr[i] * scale * w[i];
        sxn[i] = v;
        g_xn2[(size_t)t * HID + i] = v;
    }
    __syncthreads();
    int warp = tid >> 5, lane = tid & 31;
    float s0 = 0.f, s1 = 0.f;
    for (int k = lane; k < HID; k += 32) {
        float xv = sxn[k];
        s0 += xv * Wr[k * NE + 2 * warp];
        s1 += xv * Wr[k * NE + 2 * warp + 1];
    }
#pragma unroll
    for (int o = 16; o > 0; o >>= 1) {
        s0 += __shfl_xor_sync(0xffffffffu, s0, o);
        s1 += __shfl_xor_sync(0xffffffffu, s1, o);
    }
    if (lane == 0) { lg[2 * warp] = s0; lg[2 * warp + 1] = s1; }
    __syncthreads();
    if (tid == 0) {
        int b0 = 0;
        float v0 = lg[0];
        for (int e = 1; e < NE; e++)
            if (lg[e] > v0) { v0 = lg[e]; b0 = e; }
        int b1 = -1;
        float v1 = -3e38f;
        for (int e = 0; e < NE; e++)
            if (e != b0 && lg[e] > v1) { v1 = lg[e]; b1 = e; }
        float w0 = 1.f / (1.f + __expf(v1 - v0));
        g_eid[2 * t] = b0;
        g_eid[2 * t + 1] = b1;
        g_ew[2 * t] = w0;
        g_ew[2 * t + 1] = 1.f - w0;
        atomicAdd(&g_cnt[b0], 1);
        atomicAdd(&g_cnt[b1], 1);
    }
}

// ---------------------------------------------------------------------------
// Routing plumbing
// ---------------------------------------------------------------------------
__global__ void k_reset(void) {
    if (threadIdx.x < NE) {
        g_cnt[threadIdx.x] = 0;
        g_cur[threadIdx.x] = 0;
    }
}

__global__ void k_scan(void) {
    if (threadIdx.x == 0) {
        int a = 0;
        for (int e = 0; e < NE; e++) {
            g_off[e] = a;
            a += g_cnt[e];
        }
        g_off[NE] = a;
    }
}

__global__ void k_scatter(void) {
    int t = blockIdx.x * blockDim.x + threadIdx.x;
    if (t >= SEQ) return;
#pragma unroll
    for (int slot = 0; slot < 2; slot++) {
        int e = g_eid[2 * t + slot];
        int pos = g_off[e] + atomicAdd(&g_cur[e], 1);
        g_ptok[pos] = t;
        g_tslot[2 * t + slot] = pos;
    }
}

__global__ void k_combine(float* __restrict__ out) {
    int t = blockIdx.x;
    int i = threadIdx.x;
    int p0 = g_tslot[2 * t], p1 = g_tslot[2 * t + 1];
    float w0 = g_ew[2 * t], w1 = g_ew[2 * t + 1];
    float4 a = reinterpret_cast<const float4*>(g_h1 + (size_t)t * HID)[i];
    float4 b = reinterpret_cast<const float4*>(g_Dn + (size_t)p0 * HID)[i];
    float4 c = reinterpret_cast<const float4*>(g_Dn + (size_t)p1 * HID)[i];
    float4 o = make_float4(a.x + w0 * b.x + w1 * c.x,
                           a.y + w0 * b.y + w1 * c.y,
                           a.z + w0 * b.z + w1 * c.z,
                           a.w + w0 * b.w + w1 * c.w);
    reinterpret_cast<float4*>(out + (size_t)t * HID)[i] = o;
}

// ---------------------------------------------------------------------------
// Launch
// ---------------------------------------------------------------------------
extern "C" void kernel_launch(void* const* d_in, const int* in_sizes, int n_in,
                              void* d_out, int out_size) {
    (void)in_sizes; (void)n_in; (void)out_size;
    const float* x        = (const float*)d_in[0];
    const float* norm1_w  = (const float*)d_in[1];
    const float* w_qkv    = (const float*)d_in[2];
    const float* w_out    = (const float*)d_in[3];
    const float* norm2_w  = (const float*)d_in[4];
    const float* w_router = (const float*)d_in[5];
    const float* w_gateup = (const float*)d_in[6];
    const float* w_down   = (const float*)d_in[7];
    float* out = (float*)d_out;

    cudaFuncSetAttribute(k_attn, cudaFuncAttributeMaxDynamicSharedMemorySize,
                         ATT_SMEM_BYTES);
    cudaFuncSetAttribute(k_gemm_qkv, cudaFuncAttributeMaxDynamicSharedMemorySize,
                         SMEM_SINGLE_B);
    cudaFuncSetAttribute(k_gemm_out, cudaFuncAttributeMaxDynamicSharedMemorySize,
                         SMEM_DUAL_B);
    cudaFuncSetAttribute(k_moe_gemm1, cudaFuncAttributeMaxDynamicSharedMemorySize,
                         SMEM_DUAL_B);
    cudaFuncSetAttribute(k_moe_gemm2, cudaFuncAttributeMaxDynamicSharedMemorySize,
                         SMEM_DUAL_B);

    k_reset<<<1, 32>>>();
    k_ropetab<<<SEQ * 32 / 256, 256>>>();
    k_rmsnorm1<<<SEQ, 256>>>(x, norm1_w);
    k_gemm_qkv<<<dim3(SEQ / 128, QKVC / 128), 256, SMEM_SINGLE_B>>>(w_qkv);
    k_attn<<<dim3(SEQ / 64, NQ), 256, ATT_SMEM_BYTES>>>();
    k_gemm_out<<<dim3(SEQ / 128, HID / 256), 256, SMEM_DUAL_B>>>(w_out, x);
    k_rms2router<<<SEQ, 256>>>(norm2_w, w_router);
    k_scan<<<1, 32>>>();
    k_scatter<<<(SEQ + 255) / 256, 256>>>();
    k_moe_gemm1<<<dim3(NE * 16, FF / 128), 256, SMEM_DUAL_B>>>(w_gateup);
    k_moe_gemm2<<<dim3(NE * 16, HID / 256), 256, SMEM_DUAL_B>>>(w_down);
    k_combine<<<SEQ, 192>>>(out);
}

// round 10
// speedup vs baseline: 1.6996x; 1.0026x over previous
#include <cuda_runtime.h>
#include <math.h>

// ---------------------------------------------------------------------------
// Constants
// ---------------------------------------------------------------------------
#define SEQ   2048
#define HID   768
#define NQ    12
#define NKV   3
#define HD    64
#define QKVC  1152
#define NE    16
#define FF    1536
#define SLOTS 4096

// GEMM smem geometry (3-stage pipeline)
#define SA_STRIDE 20
#define SB_STRIDE 136          // 8c+8ni+g -> conflict-free B frags
#define SA_STAGE  (128 * SA_STRIDE)
#define SB_STAGE  (16 * SB_STRIDE)
#define SMEM_SINGLE_B ((3 * SA_STAGE + 3 * SB_STAGE) * 4)
#define SMEM_DUAL_B   ((3 * SA_STAGE + 6 * SB_STAGE) * 4)

// ---------------------------------------------------------------------------
// Device scratch
// ---------------------------------------------------------------------------
__device__ float g_xn1[SEQ * HID];
__device__ float g_Q[NQ * SEQ * HD];
__device__ float g_K[NKV * SEQ * HD];
__device__ float g_V[NKV * SEQ * HD];
__device__ float g_attn[SEQ * HID];
__device__ float g_h1[SEQ * HID];
__device__ float g_xn2[SEQ * HID];
__device__ float g_cos[SEQ * 32];
__device__ float g_sin[SEQ * 32];
__device__ int   g_eid[SLOTS];
__device__ float g_ew[SLOTS];
__device__ int   g_cnt[NE];
__device__ int   g_off[NE + 1];
__device__ int   g_cur[NE];
__device__ int   g_ptok[SLOTS];
__device__ int   g_tslot[SLOTS];
__device__ float g_Hact[(size_t)SLOTS * FF];
__device__ float g_Dn[(size_t)SLOTS * HID];

// ---------------------------------------------------------------------------
// Helpers
// ---------------------------------------------------------------------------
__device__ __forceinline__ void mma_tf32(float d[4], const unsigned a[4],
                                         const unsigned b[2]) {
    asm volatile(
        "mma.sync.aligned.m16n8k8.row.col.f32.tf32.tf32.f32 "
        "{%0,%1,%2,%3}, {%4,%5,%6,%7}, {%8,%9}, {%0,%1,%2,%3};"
        : "+f"(d[0]), "+f"(d[1]), "+f"(d[2]), "+f"(d[3])
        : "r"(a[0]), "r"(a[1]), "r"(a[2]), "r"(a[3]),
          "r"(b[0]), "r"(b[1]));
}

__device__ __forceinline__ void cp16(void* smem_dst, const void* gmem_src, bool pred) {
    unsigned d = (unsigned)__cvta_generic_to_shared(smem_dst);
    int sz = pred ? 16 : 0;
    asm volatile("cp.async.cg.shared.global [%0], [%1], 16, %2;"
                 :: "r"(d), "l"(gmem_src), "r"(sz) : "memory");
}

// ---------------------------------------------------------------------------
// RoPE table: accurate sincosf once, table-lookup everywhere else
// ---------------------------------------------------------------------------
__global__ void k_ropetab(void) {
    int idx = blockIdx.x * blockDim.x + threadIdx.x;   // SEQ*32
    int s = idx >> 5, i = idx & 31;
    float inv = powf(10000.f, -(float)(2 * i) / 64.f);
    float sn, cs;
    sincosf((float)s * inv, &sn, &cs);
    g_cos[idx] = cs;
    g_sin[idx] = sn;
}

// ---------------------------------------------------------------------------
// RMSNorm 1
// ---------------------------------------------------------------------------
__global__ void k_rmsnorm1(const float* __restrict__ x, const float* __restrict__ w) {
    int row = blockIdx.x;
    const float* xr = x + (size_t)row * HID;
    float s = 0.f;
    for (int i = threadIdx.x; i < HID; i += 256) {
        float v = xr[i];
        s += v * v;
    }
    __shared__ float red[256];
    red[threadIdx.x] = s;
    __syncthreads();
    for (int o = 128; o > 0; o >>= 1) {
        if (threadIdx.x < o) red[threadIdx.x] += red[threadIdx.x + o];
        __syncthreads();
    }
    float scale = rsqrtf(red[0] / (float)HID + 1e-6f);
    for (int i = threadIdx.x; i < HID; i += 256)
        g_xn1[(size_t)row * HID + i] = xr[i] * scale * w[i];
}

// ---------------------------------------------------------------------------
// Single-B TF32 GEMM core (3-stage cp.async)
// ---------------------------------------------------------------------------
__device__ __forceinline__ void gemm_single3(
    const float* Ar0, const float* Ar1, bool p0, bool p1,
    const float* Br0, const float* Br1, int ldb,
    int K, unsigned* SA, unsigned* SB, float acc[4][4][4])
{
    int tid = threadIdx.x;
    int warp = tid >> 5, lane = tid & 31;
    int wm = warp >> 2, wn = warp & 3;
    int g = lane >> 2, c = lane & 3;
    int ar0 = tid >> 2, ar1 = ar0 + 64;
    int akq = (tid & 3) * 4;
    int bkr0 = tid >> 5, bkr1 = bkr0 + 8;
    int bc4 = (tid & 31) * 4;

#define ST1(s, k0)                                                            \
    do {                                                                      \
        unsigned* a_ = SA + (s) * SA_STAGE;                                   \
        unsigned* b_ = SB + (s) * SB_STAGE;                                   \
        cp16(a_ + ar0 * SA_STRIDE + akq, Ar0 + (k0), p0);                     \
        cp16(a_ + ar1 * SA_STRIDE + akq, Ar1 + (k0), p1);                     \
        cp16(b_ + bkr0 * SB_STRIDE + bc4, Br0 + (size_t)(k0) * ldb, true);    \
        cp16(b_ + bkr1 * SB_STRIDE + bc4, Br1 + (size_t)(k0) * ldb, true);    \
        asm volatile("cp.async.commit_group;" ::: "memory");                  \
    } while (0)

    ST1(0, 0);
    ST1(1, 16);
    int buf = 0;
    for (int k0 = 0; k0 < K; k0 += 16) {
        if (k0 + 32 < K) {
            asm volatile("cp.async.wait_group 1;" ::: "memory");
            __syncthreads();
            ST1(buf == 0 ? 2 : buf - 1, k0 + 32);
        } else {
            asm volatile("cp.async.wait_group 0;" ::: "memory");
            __syncthreads();
        }
        unsigned* a_ = SA + buf * SA_STAGE;
        unsigned* b_ = SB + buf * SB_STAGE;
#pragma unroll
        for (int kk = 0; kk < 16; kk += 8) {
            unsigned af[4][4];
#pragma unroll
            for (int mi = 0; mi < 4; mi++) {
                int m = wm * 64 + mi * 16;
                af[mi][0] = a_[(m + g) * SA_STRIDE + kk + c];
                af[mi][1] = a_[(m + g + 8) * SA_STRIDE + kk + c];
                af[mi][2] = a_[(m + g) * SA_STRIDE + kk + c + 4];
                af[mi][3] = a_[(m + g + 8) * SA_STRIDE + kk + c + 4];
            }
#pragma unroll
            for (int ni = 0; ni < 4; ni++) {
                int n = wn * 32 + ni * 8 + g;
                unsigned bf[2];
                bf[0] = b_[(kk + c) * SB_STRIDE + n];
                bf[1] = b_[(kk + c + 4) * SB_STRIDE + n];
#pragma unroll
                for (int mi = 0; mi < 4; mi++)
                    mma_tf32(acc[mi][ni], af[mi], bf);
            }
        }
        buf = (buf == 2) ? 0 : buf + 1;
    }
#undef ST1
}

// ---------------------------------------------------------------------------
// Dual-B TF32 GEMM core
// ---------------------------------------------------------------------------
__device__ __forceinline__ void gemm_dual3(
    const float* Ar0, const float* Ar1, bool p0, bool p1,
    const float* B0r0, const float* B0r1,
    const float* B1r0, const float* B1r1, int ldb,
    int K, unsigned* SA, unsigned* SB0, unsigned* SB1,
    float accg[4][4][4], float accu[4][4][4])
{
    int tid = threadIdx.x;
    int warp = tid >> 5, lane = tid & 31;
    int wm = warp >> 2, wn = warp & 3;
    int g = lane >> 2, c = lane & 3;
    int ar0 = tid >> 2, ar1 = ar0 + 64;
    int akq = (tid & 3) * 4;
    int bkr0 = tid >> 5, bkr1 = bkr0 + 8;
    int bc4 = (tid & 31) * 4;

#define STD(s, k0)                                                            \
    do {                                                                      \
        unsigned* a_  = SA + (s) * SA_STAGE;                                  \
        unsigned* b0_ = SB0 + (s) * SB_STAGE;                                 \
        unsigned* b1_ = SB1 + (s) * SB_STAGE;                                 \
        cp16(a_ + ar0 * SA_STRIDE + akq, Ar0 + (k0), p0);                     \
        cp16(a_ + ar1 * SA_STRIDE + akq, Ar1 + (k0), p1);                     \
        cp16(b0_ + bkr0 * SB_STRIDE + bc4, B0r0 + (size_t)(k0) * ldb, true);  \
        cp16(b0_ + bkr1 * SB_STRIDE + bc4, B0r1 + (size_t)(k0) * ldb, true);  \
        cp16(b1_ + bkr0 * SB_STRIDE + bc4, B1r0 + (size_t)(k0) * ldb, true);  \
        cp16(b1_ + bkr1 * SB_STRIDE + bc4, B1r1 + (size_t)(k0) * ldb, true);  \
        asm volatile("cp.async.commit_group;" ::: "memory");                  \
    } while (0)

    STD(0, 0);
    STD(1, 16);
    int buf = 0;
    for (int k0 = 0; k0 < K; k0 += 16) {
        if (k0 + 32 < K) {
            asm volatile("cp.async.wait_group 1;" ::: "memory");
            __syncthreads();
            STD(buf == 0 ? 2 : buf - 1, k0 + 32);
        } else {
            asm volatile("cp.async.wait_group 0;" ::: "memory");
            __syncthreads();
        }
        unsigned* a_  = SA + buf * SA_STAGE;
        unsigned* b0_ = SB0 + buf * SB_STAGE;
        unsigned* b1_ = SB1 + buf * SB_STAGE;
#pragma unroll
        for (int kk = 0; kk < 16; kk += 8) {
            unsigned af[4][4];
#pragma unroll
            for (int mi = 0; mi < 4; mi++) {
                int m = wm * 64 + mi * 16;
                af[mi][0] = a_[(m + g) * SA_STRIDE + kk + c];
                af[mi][1] = a_[(m + g + 8) * SA_STRIDE + kk + c];
                af[mi][2] = a_[(m + g) * SA_STRIDE + kk + c + 4];
                af[mi][3] = a_[(m + g + 8) * SA_STRIDE + kk + c + 4];
            }
#pragma unroll
            for (int ni = 0; ni < 4; ni++) {
                int n = wn * 32 + ni * 8 + g;
                unsigned bf0[2], bf1[2];
                bf0[0] = b0_[(kk + c) * SB_STRIDE + n];
                bf0[1] = b0_[(kk + c + 4) * SB_STRIDE + n];
                bf1[0] = b1_[(kk + c) * SB_STRIDE + n];
                bf1[1] = b1_[(kk + c + 4) * SB_STRIDE + n];
#pragma unroll
                for (int mi = 0; mi < 4; mi++) {
                    mma_tf32(accg[mi][ni], af[mi], bf0);
                    mma_tf32(accu[mi][ni], af[mi], bf1);
                }
            }
        }
        buf = (buf == 2) ? 0 : buf + 1;
    }
#undef STD
}

// ---------------------------------------------------------------------------
// QKV projection + fused RoPE epilogue (table-based) -> g_Q / g_K / g_V
// ---------------------------------------------------------------------------
__global__ void __launch_bounds__(256) k_gemm_qkv(const float* __restrict__ W) {
    extern __shared__ unsigned dsm[];
    int mb = blockIdx.x, nb = blockIdx.y;
    int tid = threadIdx.x;
    float acc[4][4][4] = {};
    {
        int ar0 = tid >> 2, ar1 = ar0 + 64;
        int akq = (tid & 3) * 4;
        int bkr0 = tid >> 5, bkr1 = bkr0 + 8;
        int bc4 = (tid & 31) * 4;
        const float* A = g_xn1 + (size_t)mb * 128 * HID;
        const float* B = W + nb * 128;
        gemm_single3(A + (size_t)ar0 * HID + akq, A + (size_t)ar1 * HID + akq,
                     true, true,
                     B + (size_t)bkr0 * QKVC + bc4, B + (size_t)bkr1 * QKVC + bc4,
                     QKVC, HID, dsm, dsm + 3 * SA_STAGE, acc);
    }
    int warp = tid >> 5, lane = tid & 31;
    int wm = warp >> 2, wn = warp & 3, g = lane >> 2, c = lane & 3;
#pragma unroll
    for (int mi = 0; mi < 4; mi++) {
#pragma unroll
        for (int ni = 0; ni < 4; ni++) {
            int r   = mb * 128 + wm * 64 + mi * 16 + g;
            int col = nb * 128 + wn * 32 + ni * 8 + 2 * c;
            int dm  = col & 63;
            int pi  = dm >> 1;
            float a0 = acc[mi][ni][0], a1 = acc[mi][ni][1];
            float b0 = acc[mi][ni][2], b1 = acc[mi][ni][3];
            if (col < NQ * HD) {
                int hh = col >> 6;
                float cs0 = g_cos[r * 32 + pi],       sn0 = g_sin[r * 32 + pi];
                float cs1 = g_cos[(r + 8) * 32 + pi], sn1 = g_sin[(r + 8) * 32 + pi];
                float* d0 = g_Q + ((size_t)hh * SEQ + r) * HD + dm;
                float* d1 = g_Q + ((size_t)hh * SEQ + r + 8) * HD + dm;
                *reinterpret_cast<float2*>(d0) = make_float2(a0 * cs0 - a1 * sn0, a0 * sn0 + a1 * cs0);
                *reinterpret_cast<float2*>(d1) = make_float2(b0 * cs1 - b1 * sn1, b0 * sn1 + b1 * cs1);
            } else if (col < (NQ + NKV) * HD) {
                int hh = (col - NQ * HD) >> 6;
                float cs0 = g_cos[r * 32 + pi],       sn0 = g_sin[r * 32 + pi];
                float cs1 = g_cos[(r + 8) * 32 + pi], sn1 = g_sin[(r + 8) * 32 + pi];
                float* d0 = g_K + ((size_t)hh * SEQ + r) * HD + dm;
                float* d1 = g_K + ((size_t)hh * SEQ + r + 8) * HD + dm;
                *reinterpret_cast<float2*>(d0) = make_float2(a0 * cs0 - a1 * sn0, a0 * sn0 + a1 * cs0);
                *reinterpret_cast<float2*>(d1) = make_float2(b0 * cs1 - b1 * sn1, b0 * sn1 + b1 * cs1);
            } else {
                int hh = (col - (NQ + NKV) * HD) >> 6;
                float* d0 = g_V + ((size_t)hh * SEQ + r) * HD + dm;
                float* d1 = g_V + ((size_t)hh * SEQ + r + 8) * HD + dm;
                *reinterpret_cast<float2*>(d0) = make_float2(a0, a1);
                *reinterpret_cast<float2*>(d1) = make_float2(b0, b1);
            }
        }
    }
}

// ---------------------------------------------------------------------------
// Out projection + residual (dual-B): g_h1 = x + g_attn @ w_out
// ---------------------------------------------------------------------------
__global__ void __launch_bounds__(256) k_gemm_out(const float* __restrict__ W,
                                                  const float* __restrict__ xres) {
    extern __shared__ unsigned dsm[];
    int mb = blockIdx.x, nb = blockIdx.y;
    int tid = threadIdx.x;
    float accg[4][4][4] = {};
    float accu[4][4][4] = {};
    {
        int ar0 = tid >> 2, ar1 = ar0 + 64;
        int akq = (tid & 3) * 4;
        int bkr0 = tid >> 5, bkr1 = bkr0 + 8;
        int bc4 = (tid & 31) * 4;
        const float* A  = g_attn + (size_t)mb * 128 * HID;
        const float* B0 = W + nb * 128;
        const float* B1 = B0 + 384;
        gemm_dual3(A + (size_t)ar0 * HID + akq, A + (size_t)ar1 * HID + akq, true, true,
                   B0 + (size_t)bkr0 * HID + bc4, B0 + (size_t)bkr1 * HID + bc4,
                   B1 + (size_t)bkr0 * HID + bc4, B1 + (size_t)bkr1 * HID + bc4,
                   HID, HID, dsm, dsm + 3 * SA_STAGE, dsm + 3 * SA_STAGE + 3 * SB_STAGE,
                   accg, accu);
    }
    int warp = tid >> 5, lane = tid & 31;
    int wm = warp >> 2, wn = warp & 3, g = lane >> 2, c = lane & 3;
#pragma unroll
    for (int mi = 0; mi < 4; mi++) {
#pragma unroll
        for (int ni = 0; ni < 4; ni++) {
            int r = mb * 128 + wm * 64 + mi * 16 + g;
            int col0 = nb * 128 + wn * 32 + ni * 8 + 2 * c;
#pragma unroll
            for (int half = 0; half < 2; half++) {
                float* ac = half ? accu[mi][ni] : accg[mi][ni];
                int col = col0 + half * 384;
                size_t o0 = (size_t)r * HID + col;
                size_t o1 = (size_t)(r + 8) * HID + col;
                float2 x0 = *reinterpret_cast<const float2*>(xres + o0);
                float2 x1 = *reinterpret_cast<const float2*>(xres + o1);
                *reinterpret_cast<float2*>(g_h1 + o0) = make_float2(x0.x + ac[0], x0.y + ac[1]);
                *reinterpret_cast<float2*>(g_h1 + o1) = make_float2(x1.x + ac[2], x1.y + ac[3]);
            }
        }
    }
}

// ---------------------------------------------------------------------------
// MoE GEMM1 (indirect A rows via ptok) fused with SiLU*up -> g_Hact
// ---------------------------------------------------------------------------
__global__ void __launch_bounds__(256) k_moe_gemm1(const float* __restrict__ Wgu) {
    extern __shared__ unsigned dsm[];
    __shared__ int sptok[128];
    int e = blockIdx.x >> 4, mb = blockIdx.x & 15, nb = blockIdx.y;
    int r0 = g_off[e];
    int rows_e = g_off[e + 1] - r0;
    int rbase = mb * 128;
    if (rbase >= rows_e) return;
    int rows = min(128, rows_e - rbase);
    int tid = threadIdx.x;
    if (tid < 128) sptok[tid] = (tid < rows) ? g_ptok[r0 + rbase + tid] : 0;
    __syncthreads();

    float accg[4][4][4] = {};
    float accu[4][4][4] = {};
    {
        int ar0 = tid >> 2, ar1 = ar0 + 64;
        int akq = (tid & 3) * 4;
        int bkr0 = tid >> 5, bkr1 = bkr0 + 8;
        int bc4 = (tid & 31) * 4;
        bool p0 = ar0 < rows, p1 = ar1 < rows;
        const float* Ar0 = g_xn2 + (size_t)sptok[ar0] * HID + akq;
        const float* Ar1 = g_xn2 + (size_t)sptok[ar1] * HID + akq;
        const float* Bg = Wgu + (size_t)e * HID * (2 * FF) + nb * 128;
        const float* Bu = Bg + FF;
        gemm_dual3(Ar0, Ar1, p0, p1,
                   Bg + (size_t)bkr0 * (2 * FF) + bc4, Bg + (size_t)bkr1 * (2 * FF) + bc4,
                   Bu + (size_t)bkr0 * (2 * FF) + bc4, Bu + (size_t)bkr1 * (2 * FF) + bc4,
                   2 * FF, HID, dsm, dsm + 3 * SA_STAGE, dsm + 3 * SA_STAGE + 3 * SB_STAGE,
                   accg, accu);
    }
    int warp = tid >> 5, lane = tid & 31;
    int wm = warp >> 2, wn = warp & 3, g = lane >> 2, c = lane & 3;
    float* Cp = g_Hact + (size_t)(r0 + rbase) * FF + nb * 128;
#pragma unroll
    for (int mi = 0; mi < 4; mi++) {
#pragma unroll
        for (int ni = 0; ni < 4; ni++) {
            int rr = wm * 64 + mi * 16 + g;
            int col = wn * 32 + ni * 8 + 2 * c;
            float h[4];
#pragma unroll
            for (int j = 0; j < 4; j++) {
                float gv = accg[mi][ni][j];
                h[j] = gv / (1.f + __expf(-gv)) * accu[mi][ni][j];
            }
            if (rr < rows)
                *reinterpret_cast<float2*>(Cp + (size_t)rr * FF + col) =
                    make_float2(h[0], h[1]);
            if (rr + 8 < rows)
                *reinterpret_cast<float2*>(Cp + (size_t)(rr + 8) * FF + col) =
                    make_float2(h[2], h[3]);
        }
    }
}

// ---------------------------------------------------------------------------
// MoE GEMM2 (dual-B): Dn[slot] = Hact[slot] @ w_down[e]
// ---------------------------------------------------------------------------
__global__ void __launch_bounds__(256) k_moe_gemm2(const float* __restrict__ Wd) {
    extern __shared__ unsigned dsm[];
    int e = blockIdx.x >> 4, mb = blockIdx.x & 15, nb = blockIdx.y;
    int r0 = g_off[e];
    int rows_e = g_off[e + 1] - r0;
    int rbase = mb * 128;
    if (rbase >= rows_e) return;
    int rows = min(128, rows_e - rbase);
    int tid = threadIdx.x;
    float accg[4][4][4] = {};
    float accu[4][4][4] = {};
    {
        int ar0 = tid >> 2, ar1 = ar0 + 64;
        int akq = (tid & 3) * 4;
        int bkr0 = tid >> 5, bkr1 = bkr0 + 8;
        int bc4 = (tid & 31) * 4;
        bool p0 = ar0 < rows, p1 = ar1 < rows;
        const float* A = g_Hact + (size_t)(r0 + rbase) * FF;
        const float* Ar0 = A + (size_t)(p0 ? ar0 : 0) * FF + akq;
        const float* Ar1 = A + (size_t)(p1 ? ar1 : 0) * FF + akq;
        const float* B0 = Wd + (size_t)e * FF * HID + nb * 128;
        const float* B1 = B0 + 384;
        gemm_dual3(Ar0, Ar1, p0, p1,
                   B0 + (size_t)bkr0 * HID + bc4, B0 + (size_t)bkr1 * HID + bc4,
                   B1 + (size_t)bkr0 * HID + bc4, B1 + (size_t)bkr1 * HID + bc4,
                   HID, FF, dsm, dsm + 3 * SA_STAGE, dsm + 3 * SA_STAGE + 3 * SB_STAGE,
                   accg, accu);
    }
    int warp = tid >> 5, lane = tid & 31;
    int wm = warp >> 2, wn = warp & 3, g = lane >> 2, c = lane & 3;
    float* Cp = g_Dn + (size_t)(r0 + rbase) * HID + nb * 128;
#pragma unroll
    for (int mi = 0; mi < 4; mi++) {
#pragma unroll
        for (int ni = 0; ni < 4; ni++) {
            int rr = wm * 64 + mi * 16 + g;
            int col0 = wn * 32 + ni * 8 + 2 * c;
#pragma unroll
            for (int half = 0; half < 2; half++) {
                float* ac = half ? accu[mi][ni] : accg[mi][ni];
                int col = col0 + half * 384;
                if (rr < rows)
                    *reinterpret_cast<float2*>(Cp + (size_t)rr * HID + col) =
                        make_float2(ac[0], ac[1]);
                if (rr + 8 < rows)
                    *reinterpret_cast<float2*>(Cp + (size_t)(rr + 8) * HID + col) =
                        make_float2(ac[2], ac[3]);
            }
        }
    }
}

// ---------------------------------------------------------------------------
// Flash attention, TF32 tensor cores, cp.async double-buffered K/V.
// P aliases the S buffer (same index read->write per thread, stride 68).
// smem: Q,K0,K1,SP @68 + V0,V1 @72 + scalars = 107 KB -> 2 CTAs/SM.
// ---------------------------------------------------------------------------
#define ATT_W (4 * (64 * 68) + 2 * (64 * 72) + 3 * 64)
#define ATT_SMEM_BYTES (ATT_W * 4)

__global__ void k_attn(void) {
    extern __shared__ unsigned smu[];
    unsigned* uQ  = smu;                    // [64][68]
    unsigned* uK0 = uQ + 64 * 68;           // [64][68]
    unsigned* uK1 = uK0 + 64 * 68;
    unsigned* uSP = uK1 + 64 * 68;          // [64][68]  S (float bits) then P
    unsigned* uV0 = uSP + 64 * 68;          // [64][72]
    unsigned* uV1 = uV0 + 64 * 72;
    float* mrow  = (float*)(uV1 + 64 * 72);
    float* lrow  = mrow + 64;
    float* arow  = lrow + 64;

    int qb = gridDim.x - 1 - blockIdx.x;
    int h  = blockIdx.y;
    int kvh = h >> 2;
    int tid = threadIdx.x;
    int warp = tid >> 5, lane = tid & 31;
    int wm = warp >> 2, wn = warp & 3;
    int g  = lane >> 2, c = lane & 3;

    const float* Kbase = g_K + (size_t)kvh * SEQ * HD;
    const float* Vbase = g_V + (size_t)kvh * SEQ * HD;

#define ATT_ISSUE(buf_, kb_)                                                  \
    do {                                                                      \
        unsigned* dK = (buf_) ? uK1 : uK0;                                    \
        unsigned* dV = (buf_) ? uV1 : uV0;                                    \
        const float* Kb_ = Kbase + (size_t)(kb_) * 64 * HD;                   \
        const float* Vb_ = Vbase + (size_t)(kb_) * 64 * HD;                   \
        _Pragma("unroll")                                                     \
        for (int it = 0; it < 4; it++) {                                      \
            int e_ = tid + it * 256;                                          \
            int r_ = e_ >> 4;                                                 \
            int q_ = (e_ & 15) * 4;                                           \
            cp16(dK + r_ * 68 + q_, Kb_ + r_ * HD + q_, true);                \
            cp16(dV + r_ * 72 + q_, Vb_ + r_ * HD + q_, true);                \
        }                                                                     \
        asm volatile("cp.async.commit_group;" ::: "memory");                  \
    } while (0)

    ATT_ISSUE(0, 0);
    if (qb > 0) ATT_ISSUE(1, 1);

    const float* Qb = g_Q + ((size_t)h * SEQ + qb * 64) * HD;
    for (int e = tid; e < 4096; e += 256) {
        int r = e >> 6, d = e & 63;
        uQ[r * 68 + d] = __float_as_uint(Qb[r * HD + d] * 0.125f);
    }
    if (tid < 64) { mrow[tid] = -1e30f; lrow[tid] = 0.f; }

    float oacc[2][2][4] = {};
    for (int kb = 0; kb <= qb; kb++) {
        int buf = kb & 1;
        if (kb < qb)
            asm volatile("cp.async.wait_group 1;" ::: "memory");
        else
            asm volatile("cp.async.wait_group 0;" ::: "memory");
        __syncthreads();
        unsigned* cK = buf ? uK1 : uK0;
        unsigned* cV = buf ? uV1 : uV0;

        // ---- S = Q @ K^T ----
        float sacc[2][2][4] = {};
#pragma unroll
        for (int kk = 0; kk < 64; kk += 8) {
            unsigned af[2][4];
#pragma unroll
            for (int mi = 0; mi < 2; mi++) {
                int m = wm * 32 + mi * 16;
                af[mi][0] = uQ[(m + g) * 68 + kk + c];
                af[mi][1] = uQ[(m + g + 8) * 68 + kk + c];
                af[mi][2] = uQ[(m + g) * 68 + kk + c + 4];
                af[mi][3] = uQ[(m + g + 8) * 68 + kk + c + 4];
            }
#pragma unroll
            for (int ni = 0; ni < 2; ni++) {
                int n = wn * 16 + ni * 8 + g;
                unsigned bf[2];
                bf[0] = cK[n * 68 + kk + c];
                bf[1] = cK[n * 68 + kk + c + 4];
#pragma unroll
                for (int mi = 0; mi < 2; mi++)
                    mma_tf32(sacc[mi][ni], af[mi], bf);
            }
        }
        bool diag = (kb == qb);
#pragma unroll
        for (int mi = 0; mi < 2; mi++) {
#pragma unroll
            for (int ni = 0; ni < 2; ni++) {
                int r0 = wm * 32 + mi * 16 + g;
                int cl = wn * 16 + ni * 8 + 2 * c;
                float v0 = sacc[mi][ni][0], v1 = sacc[mi][ni][1];
                float v2 = sacc[mi][ni][2], v3 = sacc[mi][ni][3];
                if (diag) {
                    if (cl > r0)     v0 = -1e30f;
                    if (cl + 1 > r0) v1 = -1e30f;
                    if (cl > r0 + 8)     v2 = -1e30f;
                    if (cl + 1 > r0 + 8) v3 = -1e30f;
                }
                uSP[r0 * 68 + cl]           = __float_as_uint(v0);
                uSP[r0 * 68 + cl + 1]       = __float_as_uint(v1);
                uSP[(r0 + 8) * 68 + cl]     = __float_as_uint(v2);
                uSP[(r0 + 8) * 68 + cl + 1] = __float_as_uint(v3);
            }
        }
        __syncthreads();

        // ---- online softmax (4 lanes/row), P written in place over S ----
        {
            int i  = tid >> 2;
            int jq = (tid & 3) * 16;
            float sv[16];
            float mx = -1e30f;
#pragma unroll
            for (int j = 0; j < 16; j++) {
                sv[j] = __uint_as_float(uSP[i * 68 + jq + j]);
                mx = fmaxf(mx, sv[j]);
            }
            mx = fmaxf(mx, __shfl_xor_sync(0xffffffffu, mx, 1));
            mx = fmaxf(mx, __shfl_xor_sync(0xffffffffu, mx, 2));
            float mold = mrow[i];
            mx = fmaxf(mx, mold);
            float sum = 0.f;
#pragma unroll
            for (int j = 0; j < 16; j++) {
                float p = __expf(sv[j] - mx);
                uSP[i * 68 + jq + j] = __float_as_uint(p);
                sum += p;
            }
            sum += __shfl_xor_sync(0xffffffffu, sum, 1);
            sum += __shfl_xor_sync(0xffffffffu, sum, 2);
            if ((tid & 3) == 0) {
                float al = __expf(mold - mx);
                lrow[i] = lrow[i] * al + sum;
                mrow[i] = mx;
                arow[i] = al;
            }
        }
        __syncthreads();

        // ---- rescale + O += P @ V ----
#pragma unroll
        for (int mi = 0; mi < 2; mi++) {
            float a0 = arow[wm * 32 + mi * 16 + g];
            float a1 = arow[wm * 32 + mi * 16 + g + 8];
#pragma unroll
            for (int ni = 0; ni < 2; ni++) {
                oacc[mi][ni][0] *= a0;
                oacc[mi][ni][1] *= a0;
                oacc[mi][ni][2] *= a1;
                oacc[mi][ni][3] *= a1;
            }
        }
#pragma unroll
        for (int kk = 0; kk < 64; kk += 8) {
            unsigned af[2][4];
#pragma unroll
            for (int mi = 0; mi < 2; mi++) {
                int m = wm * 32 + mi * 16;
                af[mi][0] = uSP[(m + g) * 68 + kk + c];
                af[mi][1] = uSP[(m + g + 8) * 68 + kk + c];
                af[mi][2] = uSP[(m + g) * 68 + kk + c + 4];
                af[mi][3] = uSP[(m + g + 8) * 68 + kk + c + 4];
            }
#pragma unroll
            for (int ni = 0; ni < 2; ni++) {
                int n = wn * 16 + ni * 8 + g;
                unsigned bf[2];
                bf[0] = cV[(kk + c) * 72 + n];
                bf[1] = cV[(kk + c + 4) * 72 + n];
#pragma unroll
                for (int mi = 0; mi < 2; mi++)
                    mma_tf32(oacc[mi][ni], af[mi], bf);
            }
        }
        // prefetch kb+2 into this buffer (its readers are done)
        if (kb + 2 <= qb) {
            __syncthreads();
            ATT_ISSUE(buf, kb + 2);
        }
    }

    __syncthreads();
#pragma unroll
    for (int mi = 0; mi < 2; mi++) {
        int rl0 = wm * 32 + mi * 16 + g;
        float i0 = 1.f / lrow[rl0];
        float i1 = 1.f / lrow[rl0 + 8];
        int gr0 = qb * 64 + rl0;
#pragma unroll
        for (int ni = 0; ni < 2; ni++) {
            int col = h * HD + wn * 16 + ni * 8 + 2 * c;
            *reinterpret_cast<float2*>(g_attn + (size_t)gr0 * HID + col) =
                make_float2(oacc[mi][ni][0] * i0, oacc[mi][ni][1] * i0);
            *reinterpret_cast<float2*>(g_attn + (size_t)(gr0 + 8) * HID + col) =
                make_float2(oacc[mi][ni][2] * i1, oacc[mi][ni][3] * i1);
        }
    }
#undef ATT_ISSUE
}

// ---------------------------------------------------------------------------
// Fused RMSNorm2 + router (fp32)
// ---------------------------------------------------------------------------
__global__ void k_rms2router(const float* __restrict__ w, const float* __restrict__ Wr) {
    int t = blockIdx.x;
    int tid = threadIdx.x;
    __shared__ float sxn[HID];
    __shared__ float red[256];
    __shared__ float lg[NE];
    const float* xr = g_h1 + (size_t)t * HID;
    float s = 0.f;
    for (int i = tid; i < HID; i += 256) {
        float v = xr[i];
        s += v * v;
    }
    red[tid] = s;
    __syncthreads();
    for (int o = 128; o > 0; o >>= 1) {
        if (tid < o) red[tid] += red[tid + o];
        __syncthreads();
    }
    float scale = rsqrtf(red[0] / (float)HID + 1e-6f);
    for (int i = tid; i < HID; i += 256) {
        float v = xr[i] * scale * w[i];
        sxn[i] = v;
        g_xn2[(size_t)t * HID + i] = v;
    }
    __syncthreads();
    int warp = tid >> 5, lane = tid & 31;
    float s0 = 0.f, s1 = 0.f;
    for (int k = lane; k < HID; k += 32) {
        float xv = sxn[k];
        s0 += xv * Wr[k * NE + 2 * warp];
        s1 += xv * Wr[k * NE + 2 * warp + 1];
    }
#pragma unroll
    for (int o = 16; o > 0; o >>= 1) {
        s0 += __shfl_xor_sync(0xffffffffu, s0, o);
        s1 += __shfl_xor_sync(0xffffffffu, s1, o);
    }
    if (lane == 0) { lg[2 * warp] = s0; lg[2 * warp + 1] = s1; }
    __syncthreads();
    if (tid == 0) {
        int b0 = 0;
        float v0 = lg[0];
        for (int e = 1; e < NE; e++)
            if (lg[e] > v0) { v0 = lg[e]; b0 = e; }
        int b1 = -1;
        float v1 = -3e38f;
        for (int e = 0; e < NE; e++)
            if (e != b0 && lg[e] > v1) { v1 = lg[e]; b1 = e; }
        float w0 = 1.f / (1.f + __expf(v1 - v0));
        g_eid[2 * t] = b0;
        g_eid[2 * t + 1] = b1;
        g_ew[2 * t] = w0;
        g_ew[2 * t + 1] = 1.f - w0;
        atomicAdd(&g_cnt[b0], 1);
        atomicAdd(&g_cnt[b1], 1);
    }
}

// ---------------------------------------------------------------------------
// Routing plumbing
// ---------------------------------------------------------------------------
__global__ void k_reset(void) {
    if (threadIdx.x < NE) {
        g_cnt[threadIdx.x] = 0;
        g_cur[threadIdx.x] = 0;
    }
}

__global__ void k_scan(void) {
    if (threadIdx.x == 0) {
        int a = 0;
        for (int e = 0; e < NE; e++) {
            g_off[e] = a;
            a += g_cnt[e];
        }
        g_off[NE] = a;
    }
}

__global__ void k_scatter(void) {
    int t = blockIdx.x * blockDim.x + threadIdx.x;
    if (t >= SEQ) return;
#pragma unroll
    for (int slot = 0; slot < 2; slot++) {
        int e = g_eid[2 * t + slot];
        int pos = g_off[e] + atomicAdd(&g_cur[e], 1);
        g_ptok[pos] = t;
        g_tslot[2 * t + slot] = pos;
    }
}

__global__ void k_combine(float* __restrict__ out) {
    int t = blockIdx.x;
    int i = threadIdx.x;
    int p0 = g_tslot[2 * t], p1 = g_tslot[2 * t + 1];
    float w0 = g_ew[2 * t], w1 = g_ew[2 * t + 1];
    float4 a = reinterpret_cast<const float4*>(g_h1 + (size_t)t * HID)[i];
    float4 b = reinterpret_cast<const float4*>(g_Dn + (size_t)p0 * HID)[i];
    float4 c = reinterpret_cast<const float4*>(g_Dn + (size_t)p1 * HID)[i];
    float4 o = make_float4(a.x + w0 * b.x + w1 * c.x,
                           a.y + w0 * b.y + w1 * c.y,
                           a.z + w0 * b.z + w1 * c.z,
                           a.w + w0 * b.w + w1 * c.w);
    reinterpret_cast<float4*>(out + (size_t)t * HID)[i] = o;
}

// ---------------------------------------------------------------------------
// Launch
// ---------------------------------------------------------------------------
extern "C" void kernel_launch(void* const* d_in, const int* in_sizes, int n_in,
                              void* d_out, int out_size) {
    (void)in_sizes; (void)n_in; (void)out_size;
    const float* x        = (const float*)d_in[0];
    const float* norm1_w  = (const float*)d_in[1];
    const float* w_qkv    = (const float*)d_in[2];
    const float* w_out    = (const float*)d_in[3];
    const float* norm2_w  = (const float*)d_in[4];
    const float* w_router = (const float*)d_in[5];
    const float* w_gateup = (const float*)d_in[6];
    const float* w_down   = (const float*)d_in[7];
    float* out = (float*)d_out;

    cudaFuncSetAttribute(k_attn, cudaFuncAttributeMaxDynamicSharedMemorySize,
                         ATT_SMEM_BYTES);
    cudaFuncSetAttribute(k_gemm_qkv, cudaFuncAttributeMaxDynamicSharedMemorySize,
                         SMEM_SINGLE_B);
    cudaFuncSetAttribute(k_gemm_out, cudaFuncAttributeMaxDynamicSharedMemorySize,
                         SMEM_DUAL_B);
    cudaFuncSetAttribute(k_moe_gemm1, cudaFuncAttributeMaxDynamicSharedMemorySize,
                         SMEM_DUAL_B);
    cudaFuncSetAttribute(k_moe_gemm2, cudaFuncAttributeMaxDynamicSharedMemorySize,
                         SMEM_DUAL_B);

    k_reset<<<1, 32>>>();
    k_ropetab<<<SEQ * 32 / 256, 256>>>();
    k_rmsnorm1<<<SEQ, 256>>>(x, norm1_w);
    k_gemm_qkv<<<dim3(SEQ / 128, QKVC / 128), 256, SMEM_SINGLE_B>>>(w_qkv);
    k_attn<<<dim3(SEQ / 64, NQ), 256, ATT_SMEM_BYTES>>>();
    k_gemm_out<<<dim3(SEQ / 128, HID / 256), 256, SMEM_DUAL_B>>>(w_out, x);
    k_rms2router<<<SEQ, 256>>>(norm2_w, w_router);
    k_scan<<<1, 32>>>();
    k_scatter<<<(SEQ + 255) / 256, 256>>>();
    k_moe_gemm1<<<dim3(NE * 16, FF / 128), 256, SMEM_DUAL_B>>>(w_gateup);
    k_moe_gemm2<<<dim3(NE * 16, HID / 256), 256, SMEM_DUAL_B>>>(w_down);
    k_combine<<<SEQ, 192>>>(out);
}

// round 15
// speedup vs baseline: 1.7814x; 1.0481x over previous
#include <cuda_runtime.h>
#include <math.h>

// ---------------------------------------------------------------------------
// Constants
// ---------------------------------------------------------------------------
#define SEQ   2048
#define HID   768
#define NQ    12
#define NKV   3
#define HD    64
#define QKVC  1152
#define NE    16
#define FF    1536
#define SLOTS 4096

// GEMM smem geometry
#define SA_STRIDE 20
#define SB_STRIDE 136          // 8c+8ni+g -> conflict-free B frags
#define SA_STAGE   (128 * SA_STRIDE)
#define SA64_STAGE (64 * SA_STRIDE)
#define SB_STAGE   (16 * SB_STRIDE)
#define SMEM_DUAL_B ((3 * SA_STAGE + 6 * SB_STAGE) * 4)
#define SMEM_M64    ((3 * SA64_STAGE + 3 * SB_STAGE) * 4)

// ---------------------------------------------------------------------------
// Device scratch
// ---------------------------------------------------------------------------
__device__ float g_xn1[SEQ * HID];
__device__ float g_Q[NQ * SEQ * HD];
__device__ float g_K[NKV * SEQ * HD];
__device__ float g_V[NKV * SEQ * HD];
__device__ float g_attn[SEQ * HID];
__device__ float g_h1[SEQ * HID];
__device__ float g_xn2[SEQ * HID];
__device__ float g_cos[SEQ * 32];
__device__ float g_sin[SEQ * 32];
__device__ int   g_eid[SLOTS];
__device__ float g_ew[SLOTS];
__device__ int   g_cnt[NE];
__device__ int   g_off[NE + 1];
__device__ int   g_cur[NE];
__device__ int   g_ptok[SLOTS];
__device__ int   g_tslot[SLOTS];
__device__ float g_Hact[(size_t)SLOTS * FF];
__device__ float g_Dn[(size_t)SLOTS * HID];

// ---------------------------------------------------------------------------
// Helpers
// ---------------------------------------------------------------------------
__device__ __forceinline__ void mma_tf32(float d[4], const unsigned a[4],
                                         const unsigned b[2]) {
    asm volatile(
        "mma.sync.aligned.m16n8k8.row.col.f32.tf32.tf32.f32 "
        "{%0,%1,%2,%3}, {%4,%5,%6,%7}, {%8,%9}, {%0,%1,%2,%3};"
        : "+f"(d[0]), "+f"(d[1]), "+f"(d[2]), "+f"(d[3])
        : "r"(a[0]), "r"(a[1]), "r"(a[2]), "r"(a[3]),
          "r"(b[0]), "r"(b[1]));
}

__device__ __forceinline__ void cp16(void* smem_dst, const void* gmem_src, bool pred) {
    unsigned d = (unsigned)__cvta_generic_to_shared(smem_dst);
    int sz = pred ? 16 : 0;
    asm volatile("cp.async.cg.shared.global [%0], [%1], 16, %2;"
                 :: "r"(d), "l"(gmem_src), "r"(sz) : "memory");
}

// ---------------------------------------------------------------------------
// RoPE table
// ---------------------------------------------------------------------------
__global__ void k_ropetab(void) {
    int idx = blockIdx.x * blockDim.x + threadIdx.x;
    int s = idx >> 5, i = idx & 31;
    float inv = powf(10000.f, -(float)(2 * i) / 64.f);
    float sn, cs;
    sincosf((float)s * inv, &sn, &cs);
    g_cos[idx] = cs;
    g_sin[idx] = sn;
}

// ---------------------------------------------------------------------------
// RMSNorm 1
// ---------------------------------------------------------------------------
__global__ void k_rmsnorm1(const float* __restrict__ x, const float* __restrict__ w) {
    int row = blockIdx.x;
    const float* xr = x + (size_t)row * HID;
    float s = 0.f;
    for (int i = threadIdx.x; i < HID; i += 256) {
        float v = xr[i];
        s += v * v;
    }
    __shared__ float red[256];
    red[threadIdx.x] = s;
    __syncthreads();
    for (int o = 128; o > 0; o >>= 1) {
        if (threadIdx.x < o) red[threadIdx.x] += red[threadIdx.x + o];
        __syncthreads();
    }
    float scale = rsqrtf(red[0] / (float)HID + 1e-6f);
    for (int i = threadIdx.x; i < HID; i += 256)
        g_xn1[(size_t)row * HID + i] = xr[i] * scale * w[i];
}

// ---------------------------------------------------------------------------
// M64 single-B TF32 GEMM core: 64x128 tile, 128 threads (4 warps, 1x4),
// warp tile 64x32, 3-stage cp.async. High occupancy (~4 CTAs/SM).
// ---------------------------------------------------------------------------
__device__ __forceinline__ void gemm_m64(
    const float* Ar0, const float* Ar1, bool p0, bool p1,
    const float* Br, int ldb,
    int K, unsigned* SA, unsigned* SB, float acc[4][4][4])
{
    int tid = threadIdx.x;            // 128
    int wn = tid >> 5;                // 0..3
    int lane = tid & 31;
    int g = lane >> 2, c = lane & 3;
    int ar0 = tid >> 2, ar1 = ar0 + 32;   // A rows 0..63
    int akq = (tid & 3) * 4;
    int bkr = tid >> 5;               // B rows bkr, +4, +8, +12
    int bc4 = (tid & 31) * 4;
    const float* Brp = Br + (size_t)bkr * ldb + bc4;

#define STM64(s, k0)                                                          \
    do {                                                                      \
        unsigned* a_ = SA + (s) * SA64_STAGE;                                 \
        unsigned* b_ = SB + (s) * SB_STAGE;                                   \
        cp16(a_ + ar0 * SA_STRIDE + akq, Ar0 + (k0), p0);                     \
        cp16(a_ + ar1 * SA_STRIDE + akq, Ar1 + (k0), p1);                     \
        cp16(b_ + (bkr + 0) * SB_STRIDE + bc4, Brp + (size_t)(k0) * ldb, true);              \
        cp16(b_ + (bkr + 4) * SB_STRIDE + bc4, Brp + (size_t)((k0) + 4) * ldb, true);        \
        cp16(b_ + (bkr + 8) * SB_STRIDE + bc4, Brp + (size_t)((k0) + 8) * ldb, true);        \
        cp16(b_ + (bkr + 12) * SB_STRIDE + bc4, Brp + (size_t)((k0) + 12) * ldb, true);      \
        asm volatile("cp.async.commit_group;" ::: "memory");                  \
    } while (0)

    STM64(0, 0);
    STM64(1, 16);
    int buf = 0;
    for (int k0 = 0; k0 < K; k0 += 16) {
        if (k0 + 32 < K) {
            asm volatile("cp.async.wait_group 1;" ::: "memory");
            __syncthreads();
            STM64(buf == 0 ? 2 : buf - 1, k0 + 32);
        } else {
            asm volatile("cp.async.wait_group 0;" ::: "memory");
            __syncthreads();
        }
        unsigned* a_ = SA + buf * SA64_STAGE;
        unsigned* b_ = SB + buf * SB_STAGE;
#pragma unroll
        for (int kk = 0; kk < 16; kk += 8) {
            unsigned af[4][4];
#pragma unroll
            for (int mi = 0; mi < 4; mi++) {
                int m = mi * 16;
                af[mi][0] = a_[(m + g) * SA_STRIDE + kk + c];
                af[mi][1] = a_[(m + g + 8) * SA_STRIDE + kk + c];
                af[mi][2] = a_[(m + g) * SA_STRIDE + kk + c + 4];
                af[mi][3] = a_[(m + g + 8) * SA_STRIDE + kk + c + 4];
            }
#pragma unroll
            for (int ni = 0; ni < 4; ni++) {
                int n = wn * 32 + ni * 8 + g;
                unsigned bf[2];
                bf[0] = b_[(kk + c) * SB_STRIDE + n];
                bf[1] = b_[(kk + c + 4) * SB_STRIDE + n];
#pragma unroll
                for (int mi = 0; mi < 4; mi++)
                    mma_tf32(acc[mi][ni], af[mi], bf);
            }
        }
        buf = (buf == 2) ? 0 : buf + 1;
    }
#undef STM64
}

// ---------------------------------------------------------------------------
// Dual-B M128 TF32 GEMM core (for MoE GEMM1)
// ---------------------------------------------------------------------------
__device__ __forceinline__ void gemm_dual3(
    const float* Ar0, const float* Ar1, bool p0, bool p1,
    const float* B0r0, const float* B0r1,
    const float* B1r0, const float* B1r1, int ldb,
    int K, unsigned* SA, unsigned* SB0, unsigned* SB1,
    float accg[4][4][4], float accu[4][4][4])
{
    int tid = threadIdx.x;
    int warp = tid >> 5, lane = tid & 31;
    int wm = warp >> 2, wn = warp & 3;
    int g = lane >> 2, c = lane & 3;
    int ar0 = tid >> 2, ar1 = ar0 + 64;
    int akq = (tid & 3) * 4;
    int bkr0 = tid >> 5, bkr1 = bkr0 + 8;
    int bc4 = (tid & 31) * 4;

#define STD(s, k0)                                                            \
    do {                                                                      \
        unsigned* a_  = SA + (s) * SA_STAGE;                                  \
        unsigned* b0_ = SB0 + (s) * SB_STAGE;                                 \
        unsigned* b1_ = SB1 + (s) * SB_STAGE;                                 \
        cp16(a_ + ar0 * SA_STRIDE + akq, Ar0 + (k0), p0);                     \
        cp16(a_ + ar1 * SA_STRIDE + akq, Ar1 + (k0), p1);                     \
        cp16(b0_ + bkr0 * SB_STRIDE + bc4, B0r0 + (size_t)(k0) * ldb, true);  \
        cp16(b0_ + bkr1 * SB_STRIDE + bc4, B0r1 + (size_t)(k0) * ldb, true);  \
        cp16(b1_ + bkr0 * SB_STRIDE + bc4, B1r0 + (size_t)(k0) * ldb, true);  \
        cp16(b1_ + bkr1 * SB_STRIDE + bc4, B1r1 + (size_t)(k0) * ldb, true);  \
        asm volatile("cp.async.commit_group;" ::: "memory");                  \
    } while (0)

    STD(0, 0);
    STD(1, 16);
    int buf = 0;
    for (int k0 = 0; k0 < K; k0 += 16) {
        if (k0 + 32 < K) {
            asm volatile("cp.async.wait_group 1;" ::: "memory");
            __syncthreads();
            STD(buf == 0 ? 2 : buf - 1, k0 + 32);
        } else {
            asm volatile("cp.async.wait_group 0;" ::: "memory");
            __syncthreads();
        }
        unsigned* a_  = SA + buf * SA_STAGE;
        unsigned* b0_ = SB0 + buf * SB_STAGE;
        unsigned* b1_ = SB1 + buf * SB_STAGE;
#pragma unroll
        for (int kk = 0; kk < 16; kk += 8) {
            unsigned af[4][4];
#pragma unroll
            for (int mi = 0; mi < 4; mi++) {
                int m = wm * 64 + mi * 16;
                af[mi][0] = a_[(m + g) * SA_STRIDE + kk + c];
                af[mi][1] = a_[(m + g + 8) * SA_STRIDE + kk + c];
                af[mi][2] = a_[(m + g) * SA_STRIDE + kk + c + 4];
                af[mi][3] = a_[(m + g + 8) * SA_STRIDE + kk + c + 4];
            }
#pragma unroll
            for (int ni = 0; ni < 4; ni++) {
                int n = wn * 32 + ni * 8 + g;
                unsigned bf0[2], bf1[2];
                bf0[0] = b0_[(kk + c) * SB_STRIDE + n];
                bf0[1] = b0_[(kk + c + 4) * SB_STRIDE + n];
                bf1[0] = b1_[(kk + c) * SB_STRIDE + n];
                bf1[1] = b1_[(kk + c + 4) * SB_STRIDE + n];
#pragma unroll
                for (int mi = 0; mi < 4; mi++) {
                    mma_tf32(accg[mi][ni], af[mi], bf0);
                    mma_tf32(accu[mi][ni], af[mi], bf1);
                }
            }
        }
        buf = (buf == 2) ? 0 : buf + 1;
    }
#undef STD
}

// ---------------------------------------------------------------------------
// QKV projection (M64) + fused RoPE epilogue -> g_Q / g_K / g_V
// ---------------------------------------------------------------------------
__global__ void __launch_bounds__(128) k_gemm_qkv(const float* __restrict__ W) {
    extern __shared__ unsigned dsm[];
    int mb = blockIdx.x, nb = blockIdx.y;
    int tid = threadIdx.x;
    float acc[4][4][4] = {};
    {
        int ar0 = tid >> 2, ar1 = ar0 + 32;
        int akq = (tid & 3) * 4;
        const float* A = g_xn1 + (size_t)mb * 64 * HID;
        gemm_m64(A + (size_t)ar0 * HID + akq, A + (size_t)ar1 * HID + akq,
                 true, true, W + nb * 128, QKVC, HID,
                 dsm, dsm + 3 * SA64_STAGE, acc);
    }
    int wn = tid >> 5, lane = tid & 31;
    int g = lane >> 2, c = lane & 3;
#pragma unroll
    for (int mi = 0; mi < 4; mi++) {
#pragma unroll
        for (int ni = 0; ni < 4; ni++) {
            int r   = mb * 64 + mi * 16 + g;
            int col = nb * 128 + wn * 32 + ni * 8 + 2 * c;
            int dm  = col & 63;
            int pi  = dm >> 1;
            float a0 = acc[mi][ni][0], a1 = acc[mi][ni][1];
            float b0 = acc[mi][ni][2], b1 = acc[mi][ni][3];
            if (col < NQ * HD) {
                int hh = col >> 6;
                float cs0 = g_cos[r * 32 + pi],       sn0 = g_sin[r * 32 + pi];
                float cs1 = g_cos[(r + 8) * 32 + pi], sn1 = g_sin[(r + 8) * 32 + pi];
                float* d0 = g_Q + ((size_t)hh * SEQ + r) * HD + dm;
                float* d1 = g_Q + ((size_t)hh * SEQ + r + 8) * HD + dm;
                *reinterpret_cast<float2*>(d0) = make_float2(a0 * cs0 - a1 * sn0, a0 * sn0 + a1 * cs0);
                *reinterpret_cast<float2*>(d1) = make_float2(b0 * cs1 - b1 * sn1, b0 * sn1 + b1 * cs1);
            } else if (col < (NQ + NKV) * HD) {
                int hh = (col - NQ * HD) >> 6;
                float cs0 = g_cos[r * 32 + pi],       sn0 = g_sin[r * 32 + pi];
                float cs1 = g_cos[(r + 8) * 32 + pi], sn1 = g_sin[(r + 8) * 32 + pi];
                float* d0 = g_K + ((size_t)hh * SEQ + r) * HD + dm;
                float* d1 = g_K + ((size_t)hh * SEQ + r + 8) * HD + dm;
                *reinterpret_cast<float2*>(d0) = make_float2(a0 * cs0 - a1 * sn0, a0 * sn0 + a1 * cs0);
                *reinterpret_cast<float2*>(d1) = make_float2(b0 * cs1 - b1 * sn1, b0 * sn1 + b1 * cs1);
            } else {
                int hh = (col - (NQ + NKV) * HD) >> 6;
                float* d0 = g_V + ((size_t)hh * SEQ + r) * HD + dm;
                float* d1 = g_V + ((size_t)hh * SEQ + r + 8) * HD + dm;
                *reinterpret_cast<float2*>(d0) = make_float2(a0, a1);
                *reinterpret_cast<float2*>(d1) = make_float2(b0, b1);
            }
        }
    }
}

// ---------------------------------------------------------------------------
// Out projection + residual (M64): g_h1 = x + g_attn @ w_out
// ---------------------------------------------------------------------------
__global__ void __launch_bounds__(128) k_gemm_out(const float* __restrict__ W,
                                                  const float* __restrict__ xres) {
    extern __shared__ unsigned dsm[];
    int mb = blockIdx.x, nb = blockIdx.y;
    int tid = threadIdx.x;
    float acc[4][4][4] = {};
    {
        int ar0 = tid >> 2, ar1 = ar0 + 32;
        int akq = (tid & 3) * 4;
        const float* A = g_attn + (size_t)mb * 64 * HID;
        gemm_m64(A + (size_t)ar0 * HID + akq, A + (size_t)ar1 * HID + akq,
                 true, true, W + nb * 128, HID, HID,
                 dsm, dsm + 3 * SA64_STAGE, acc);
    }
    int wn = tid >> 5, lane = tid & 31;
    int g = lane >> 2, c = lane & 3;
#pragma unroll
    for (int mi = 0; mi < 4; mi++) {
#pragma unroll
        for (int ni = 0; ni < 4; ni++) {
            int r = mb * 64 + mi * 16 + g;
            int col = nb * 128 + wn * 32 + ni * 8 + 2 * c;
            size_t o0 = (size_t)r * HID + col;
            size_t o1 = (size_t)(r + 8) * HID + col;
            float2 x0 = *reinterpret_cast<const float2*>(xres + o0);
            float2 x1 = *reinterpret_cast<const float2*>(xres + o1);
            *reinterpret_cast<float2*>(g_h1 + o0) =
                make_float2(x0.x + acc[mi][ni][0], x0.y + acc[mi][ni][1]);
            *reinterpret_cast<float2*>(g_h1 + o1) =
                make_float2(x1.x + acc[mi][ni][2], x1.y + acc[mi][ni][3]);
        }
    }
}

// ---------------------------------------------------------------------------
// MoE GEMM1 (indirect A rows via ptok, dual-B M128) fused with SiLU*up
// ---------------------------------------------------------------------------
__global__ void __launch_bounds__(256) k_moe_gemm1(const float* __restrict__ Wgu) {
    extern __shared__ unsigned dsm[];
    __shared__ int sptok[128];
    int e = blockIdx.x >> 4, mb = blockIdx.x & 15, nb = blockIdx.y;
    int r0 = g_off[e];
    int rows_e = g_off[e + 1] - r0;
    int rbase = mb * 128;
    if (rbase >= rows_e) return;
    int rows = min(128, rows_e - rbase);
    int tid = threadIdx.x;
    if (tid < 128) sptok[tid] = (tid < rows) ? g_ptok[r0 + rbase + tid] : 0;
    __syncthreads();

    float accg[4][4][4] = {};
    float accu[4][4][4] = {};
    {
        int ar0 = tid >> 2, ar1 = ar0 + 64;
        int akq = (tid & 3) * 4;
        int bkr0 = tid >> 5, bkr1 = bkr0 + 8;
        int bc4 = (tid & 31) * 4;
        bool p0 = ar0 < rows, p1 = ar1 < rows;
        const float* Ar0 = g_xn2 + (size_t)sptok[ar0] * HID + akq;
        const float* Ar1 = g_xn2 + (size_t)sptok[ar1] * HID + akq;
        const float* Bg = Wgu + (size_t)e * HID * (2 * FF) + nb * 128;
        const float* Bu = Bg + FF;
        gemm_dual3(Ar0, Ar1, p0, p1,
                   Bg + (size_t)bkr0 * (2 * FF) + bc4, Bg + (size_t)bkr1 * (2 * FF) + bc4,
                   Bu + (size_t)bkr0 * (2 * FF) + bc4, Bu + (size_t)bkr1 * (2 * FF) + bc4,
                   2 * FF, HID, dsm, dsm + 3 * SA_STAGE, dsm + 3 * SA_STAGE + 3 * SB_STAGE,
                   accg, accu);
    }
    int warp = tid >> 5, lane = tid & 31;
    int wm = warp >> 2, wn = warp & 3, g = lane >> 2, c = lane & 3;
    float* Cp = g_Hact + (size_t)(r0 + rbase) * FF + nb * 128;
#pragma unroll
    for (int mi = 0; mi < 4; mi++) {
#pragma unroll
        for (int ni = 0; ni < 4; ni++) {
            int rr = wm * 64 + mi * 16 + g;
            int col = wn * 32 + ni * 8 + 2 * c;
            float h[4];
#pragma unroll
            for (int j = 0; j < 4; j++) {
                float gv = accg[mi][ni][j];
                h[j] = gv / (1.f + __expf(-gv)) * accu[mi][ni][j];
            }
            if (rr < rows)
                *reinterpret_cast<float2*>(Cp + (size_t)rr * FF + col) =
                    make_float2(h[0], h[1]);
            if (rr + 8 < rows)
                *reinterpret_cast<float2*>(Cp + (size_t)(rr + 8) * FF + col) =
                    make_float2(h[2], h[3]);
        }
    }
}

// ---------------------------------------------------------------------------
// MoE GEMM2 (M64): Dn[slot] = Hact[slot] @ w_down[e]
// ---------------------------------------------------------------------------
__global__ void __launch_bounds__(128) k_moe_gemm2(const float* __restrict__ Wd) {
    extern __shared__ unsigned dsm[];
    int e = blockIdx.x >> 5, mb = blockIdx.x & 31, nb = blockIdx.y;
    int r0 = g_off[e];
    int rows_e = g_off[e + 1] - r0;
    int rbase = mb * 64;
    if (rbase >= rows_e) return;
    int rows = min(64, rows_e - rbase);
    int tid = threadIdx.x;
    float acc[4][4][4] = {};
    {
        int ar0 = tid >> 2, ar1 = ar0 + 32;
        int akq = (tid & 3) * 4;
        bool p0 = ar0 < rows, p1 = ar1 < rows;
        const float* A = g_Hact + (size_t)(r0 + rbase) * FF;
        const float* Ar0 = A + (size_t)(p0 ? ar0 : 0) * FF + akq;
        const float* Ar1 = A + (size_t)(p1 ? ar1 : 0) * FF + akq;
        gemm_m64(Ar0, Ar1, p0, p1,
                 Wd + (size_t)e * FF * HID + nb * 128, HID, FF,
                 dsm, dsm + 3 * SA64_STAGE, acc);
    }
    int wn = tid >> 5, lane = tid & 31;
    int g = lane >> 2, c = lane & 3;
    float* Cp = g_Dn + (size_t)(r0 + rbase) * HID + nb * 128;
#pragma unroll
    for (int mi = 0; mi < 4; mi++) {
#pragma unroll
        for (int ni = 0; ni < 4; ni++) {
            int rr = mi * 16 + g;
            int col = wn * 32 + ni * 8 + 2 * c;
            if (rr < rows)
                *reinterpret_cast<float2*>(Cp + (size_t)rr * HID + col) =
                    make_float2(acc[mi][ni][0], acc[mi][ni][1]);
            if (rr + 8 < rows)
                *reinterpret_cast<float2*>(Cp + (size_t)(rr + 8) * HID + col) =
                    make_float2(acc[mi][ni][2], acc[mi][ni][3]);
        }
    }
}

// ---------------------------------------------------------------------------
// Flash attention (unchanged from R10 best): TF32, double-buffered K/V,
// P aliases S. 107 KB smem -> 2 CTAs/SM.
// ---------------------------------------------------------------------------
#define ATT_W (4 * (64 * 68) + 2 * (64 * 72) + 3 * 64)
#define ATT_SMEM_BYTES (ATT_W * 4)

__global__ void k_attn(void) {
    extern __shared__ unsigned smu[];
    unsigned* uQ  = smu;
    unsigned* uK0 = uQ + 64 * 68;
    unsigned* uK1 = uK0 + 64 * 68;
    unsigned* uSP = uK1 + 64 * 68;
    unsigned* uV0 = uSP + 64 * 68;
    unsigned* uV1 = uV0 + 64 * 72;
    float* mrow  = (float*)(uV1 + 64 * 72);
    float* lrow  = mrow + 64;
    float* arow  = lrow + 64;

    int qb = gridDim.x - 1 - blockIdx.x;
    int h  = blockIdx.y;
    int kvh = h >> 2;
    int tid = threadIdx.x;
    int warp = tid >> 5, lane = tid & 31;
    int wm = warp >> 2, wn = warp & 3;
    int g  = lane >> 2, c = lane & 3;

    const float* Kbase = g_K + (size_t)kvh * SEQ * HD;
    const float* Vbase = g_V + (size_t)kvh * SEQ * HD;

#define ATT_ISSUE(buf_, kb_)                                                  \
    do {                                                                      \
        unsigned* dK = (buf_) ? uK1 : uK0;                                    \
        unsigned* dV = (buf_) ? uV1 : uV0;                                    \
        const float* Kb_ = Kbase + (size_t)(kb_) * 64 * HD;                   \
        const float* Vb_ = Vbase + (size_t)(kb_) * 64 * HD;                   \
        _Pragma("unroll")                                                     \
        for (int it = 0; it < 4; it++) {                                      \
            int e_ = tid + it * 256;                                          \
            int r_ = e_ >> 4;                                                 \
            int q_ = (e_ & 15) * 4;                                           \
            cp16(dK + r_ * 68 + q_, Kb_ + r_ * HD + q_, true);                \
            cp16(dV + r_ * 72 + q_, Vb_ + r_ * HD + q_, true);                \
        }                                                                     \
        asm volatile("cp.async.commit_group;" ::: "memory");                  \
    } while (0)

    ATT_ISSUE(0, 0);
    if (qb > 0) ATT_ISSUE(1, 1);

    const float* Qb = g_Q + ((size_t)h * SEQ + qb * 64) * HD;
    for (int e = tid; e < 4096; e += 256) {
        int r = e >> 6, d = e & 63;
        uQ[r * 68 + d] = __float_as_uint(Qb[r * HD + d] * 0.125f);
    }
    if (tid < 64) { mrow[tid] = -1e30f; lrow[tid] = 0.f; }

    float oacc[2][2][4] = {};
    for (int kb = 0; kb <= qb; kb++) {
        int buf = kb & 1;
        if (kb < qb)
            asm volatile("cp.async.wait_group 1;" ::: "memory");
        else
            asm volatile("cp.async.wait_group 0;" ::: "memory");
        __syncthreads();
        unsigned* cK = buf ? uK1 : uK0;
        unsigned* cV = buf ? uV1 : uV0;

        float sacc[2][2][4] = {};
#pragma unroll
        for (int kk = 0; kk < 64; kk += 8) {
            unsigned af[2][4];
#pragma unroll
            for (int mi = 0; mi < 2; mi++) {
                int m = wm * 32 + mi * 16;
                af[mi][0] = uQ[(m + g) * 68 + kk + c];
                af[mi][1] = uQ[(m + g + 8) * 68 + kk + c];
                af[mi][2] = uQ[(m + g) * 68 + kk + c + 4];
                af[mi][3] = uQ[(m + g + 8) * 68 + kk + c + 4];
            }
#pragma unroll
            for (int ni = 0; ni < 2; ni++) {
                int n = wn * 16 + ni * 8 + g;
                unsigned bf[2];
                bf[0] = cK[n * 68 + kk + c];
                bf[1] = cK[n * 68 + kk + c + 4];
#pragma unroll
                for (int mi = 0; mi < 2; mi++)
                    mma_tf32(sacc[mi][ni], af[mi], bf);
            }
        }
        bool diag = (kb == qb);
#pragma unroll
        for (int mi = 0; mi < 2; mi++) {
#pragma unroll
            for (int ni = 0; ni < 2; ni++) {
                int r0 = wm * 32 + mi * 16 + g;
                int cl = wn * 16 + ni * 8 + 2 * c;
                float v0 = sacc[mi][ni][0], v1 = sacc[mi][ni][1];
                float v2 = sacc[mi][ni][2], v3 = sacc[mi][ni][3];
                if (diag) {
                    if (cl > r0)     v0 = -1e30f;
                    if (cl + 1 > r0) v1 = -1e30f;
                    if (cl > r0 + 8)     v2 = -1e30f;
                    if (cl + 1 > r0 + 8) v3 = -1e30f;
                }
                uSP[r0 * 68 + cl]           = __float_as_uint(v0);
                uSP[r0 * 68 + cl + 1]       = __float_as_uint(v1);
                uSP[(r0 + 8) * 68 + cl]     = __float_as_uint(v2);
                uSP[(r0 + 8) * 68 + cl + 1] = __float_as_uint(v3);
            }
        }
        __syncthreads();

        {
            int i  = tid >> 2;
            int jq = (tid & 3) * 16;
            float sv[16];
            float mx = -1e30f;
#pragma unroll
            for (int j = 0; j < 16; j++) {
                sv[j] = __uint_as_float(uSP[i * 68 + jq + j]);
                mx = fmaxf(mx, sv[j]);
            }
            mx = fmaxf(mx, __shfl_xor_sync(0xffffffffu, mx, 1));
            mx = fmaxf(mx, __shfl_xor_sync(0xffffffffu, mx, 2));
            float mold = mrow[i];
            mx = fmaxf(mx, mold);
            float sum = 0.f;
#pragma unroll
            for (int j = 0; j < 16; j++) {
                float p = __expf(sv[j] - mx);
                uSP[i * 68 + jq + j] = __float_as_uint(p);
                sum += p;
            }
            sum += __shfl_xor_sync(0xffffffffu, sum, 1);
            sum += __shfl_xor_sync(0xffffffffu, sum, 2);
            if ((tid & 3) == 0) {
                float al = __expf(mold - mx);
                lrow[i] = lrow[i] * al + sum;
                mrow[i] = mx;
                arow[i] = al;
            }
        }
        __syncthreads();

#pragma unroll
        for (int mi = 0; mi < 2; mi++) {
            float a0 = arow[wm * 32 + mi * 16 + g];
            float a1 = arow[wm * 32 + mi * 16 + g + 8];
#pragma unroll
            for (int ni = 0; ni < 2; ni++) {
                oacc[mi][ni][0] *= a0;
                oacc[mi][ni][1] *= a0;
                oacc[mi][ni][2] *= a1;
                oacc[mi][ni][3] *= a1;
            }
        }
#pragma unroll
        for (int kk = 0; kk < 64; kk += 8) {
            unsigned af[2][4];
#pragma unroll
            for (int mi = 0; mi < 2; mi++) {
                int m = wm * 32 + mi * 16;
                af[mi][0] = uSP[(m + g) * 68 + kk + c];
                af[mi][1] = uSP[(m + g + 8) * 68 + kk + c];
                af[mi][2] = uSP[(m + g) * 68 + kk + c + 4];
                af[mi][3] = uSP[(m + g + 8) * 68 + kk + c + 4];
            }
#pragma unroll
            for (int ni = 0; ni < 2; ni++) {
                int n = wn * 16 + ni * 8 + g;
                unsigned bf[2];
                bf[0] = cV[(kk + c) * 72 + n];
                bf[1] = cV[(kk + c + 4) * 72 + n];
#pragma unroll
                for (int mi = 0; mi < 2; mi++)
                    mma_tf32(oacc[mi][ni], af[mi], bf);
            }
        }
        if (kb + 2 <= qb) {
            __syncthreads();
            ATT_ISSUE(buf, kb + 2);
        }
    }

    __syncthreads();
#pragma unroll
    for (int mi = 0; mi < 2; mi++) {
        int rl0 = wm * 32 + mi * 16 + g;
        float i0 = 1.f / lrow[rl0];
        float i1 = 1.f / lrow[rl0 + 8];
        int gr0 = qb * 64 + rl0;
#pragma unroll
        for (int ni = 0; ni < 2; ni++) {
            int col = h * HD + wn * 16 + ni * 8 + 2 * c;
            *reinterpret_cast<float2*>(g_attn + (size_t)gr0 * HID + col) =
                make_float2(oacc[mi][ni][0] * i0, oacc[mi][ni][1] * i0);
            *reinterpret_cast<float2*>(g_attn + (size_t)(gr0 + 8) * HID + col) =
                make_float2(oacc[mi][ni][2] * i1, oacc[mi][ni][3] * i1);
        }
    }
#undef ATT_ISSUE
}

// ---------------------------------------------------------------------------
// Fused RMSNorm2 + router (fp32)
// ---------------------------------------------------------------------------
__global__ void k_rms2router(const float* __restrict__ w, const float* __restrict__ Wr) {
    int t = blockIdx.x;
    int tid = threadIdx.x;
    __shared__ float sxn[HID];
    __shared__ float red[256];
    __shared__ float lg[NE];
    const float* xr = g_h1 + (size_t)t * HID;
    float s = 0.f;
    for (int i = tid; i < HID; i += 256) {
        float v = xr[i];
        s += v * v;
    }
    red[tid] = s;
    __syncthreads();
    for (int o = 128; o > 0; o >>= 1) {
        if (tid < o) red[tid] += red[tid + o];
        __syncthreads();
    }
    float scale = rsqrtf(red[0] / (float)HID + 1e-6f);
    for (int i = tid; i < HID; i += 256) {
        float v = xr[i] * scale * w[i];
        sxn[i] = v;
        g_xn2[(size_t)t * HID + i] = v;
    }
    __syncthreads();
    int warp = tid >> 5, lane = tid & 31;
    float s0 = 0.f, s1 = 0.f;
    for (int k = lane; k < HID; k += 32) {
        float xv = sxn[k];
        s0 += xv * Wr[k * NE + 2 * warp];
        s1 += xv * Wr[k * NE + 2 * warp + 1];
    }
#pragma unroll
    for (int o = 16; o > 0; o >>= 1) {
        s0 += __shfl_xor_sync(0xffffffffu, s0, o);
        s1 += __shfl_xor_sync(0xffffffffu, s1, o);
    }
    if (lane == 0) { lg[2 * warp] = s0; lg[2 * warp + 1] = s1; }
    __syncthreads();
    if (tid == 0) {
        int b0 = 0;
        float v0 = lg[0];
        for (int e = 1; e < NE; e++)
            if (lg[e] > v0) { v0 = lg[e]; b0 = e; }
        int b1 = -1;
        float v1 = -3e38f;
        for (int e = 0; e < NE; e++)
            if (e != b0 && lg[e] > v1) { v1 = lg[e]; b1 = e; }
        float w0 = 1.f / (1.f + __expf(v1 - v0));
        g_eid[2 * t] = b0;
        g_eid[2 * t + 1] = b1;
        g_ew[2 * t] = w0;
        g_ew[2 * t + 1] = 1.f - w0;
        atomicAdd(&g_cnt[b0], 1);
        atomicAdd(&g_cnt[b1], 1);
    }
}

// ---------------------------------------------------------------------------
// Routing plumbing
// ---------------------------------------------------------------------------
__global__ void k_reset(void) {
    if (threadIdx.x < NE) {
        g_cnt[threadIdx.x] = 0;
        g_cur[threadIdx.x] = 0;
    }
}

__global__ void k_scan(void) {
    if (threadIdx.x == 0) {
        int a = 0;
        for (int e = 0; e < NE; e++) {
            g_off[e] = a;
            a += g_cnt[e];
        }
        g_off[NE] = a;
    }
}

__global__ void k_scatter(void) {
    int t = blockIdx.x * blockDim.x + threadIdx.x;
    if (t >= SEQ) return;
#pragma unroll
    for (int slot = 0; slot < 2; slot++) {
        int e = g_eid[2 * t + slot];
        int pos = g_off[e] + atomicAdd(&g_cur[e], 1);
        g_ptok[pos] = t;
        g_tslot[2 * t + slot] = pos;
    }
}

__global__ void k_combine(float* __restrict__ out) {
    int t = blockIdx.x;
    int i = threadIdx.x;
    int p0 = g_tslot[2 * t], p1 = g_tslot[2 * t + 1];
    float w0 = g_ew[2 * t], w1 = g_ew[2 * t + 1];
    float4 a = reinterpret_cast<const float4*>(g_h1 + (size_t)t * HID)[i];
    float4 b = reinterpret_cast<const float4*>(g_Dn + (size_t)p0 * HID)[i];
    float4 c = reinterpret_cast<const float4*>(g_Dn + (size_t)p1 * HID)[i];
    float4 o = make_float4(a.x + w0 * b.x + w1 * c.x,
                           a.y + w0 * b.y + w1 * c.y,
                           a.z + w0 * b.z + w1 * c.z,
                           a.w + w0 * b.w + w1 * c.w);
    reinterpret_cast<float4*>(out + (size_t)t * HID)[i] = o;
}

// ---------------------------------------------------------------------------
// Launch
// ---------------------------------------------------------------------------
extern "C" void kernel_launch(void* const* d_in, const int* in_sizes, int n_in,
                              void* d_out, int out_size) {
    (void)in_sizes; (void)n_in; (void)out_size;
    const float* x        = (const float*)d_in[0];
    const float* norm1_w  = (const float*)d_in[1];
    const float* w_qkv    = (const float*)d_in[2];
    const float* w_out    = (const float*)d_in[3];
    const float* norm2_w  = (const float*)d_in[4];
    const float* w_router = (const float*)d_in[5];
    const float* w_gateup = (const float*)d_in[6];
    const float* w_down   = (const float*)d_in[7];
    float* out = (float*)d_out;

    cudaFuncSetAttribute(k_attn, cudaFuncAttributeMaxDynamicSharedMemorySize,
                         ATT_SMEM_BYTES);
    cudaFuncSetAttribute(k_gemm_qkv, cudaFuncAttributeMaxDynamicSharedMemorySize,
                         SMEM_M64);
    cudaFuncSetAttribute(k_gemm_out, cudaFuncAttributeMaxDynamicSharedMemorySize,
                         SMEM_M64);
    cudaFuncSetAttribute(k_moe_gemm1, cudaFuncAttributeMaxDynamicSharedMemorySize,
                         SMEM_DUAL_B);
    cudaFuncSetAttribute(k_moe_gemm2, cudaFuncAttributeMaxDynamicSharedMemorySize,
                         SMEM_M64);

    k_reset<<<1, 32>>>();
    k_ropetab<<<SEQ * 32 / 256, 256>>>();
    k_rmsnorm1<<<SEQ, 256>>>(x, norm1_w);
    k_gemm_qkv<<<dim3(SEQ / 64, QKVC / 128), 128, SMEM_M64>>>(w_qkv);
    k_attn<<<dim3(SEQ / 64, NQ), 256, ATT_SMEM_BYTES>>>();
    k_gemm_out<<<dim3(SEQ / 64, HID / 128), 128, SMEM_M64>>>(w_out, x);
    k_rms2router<<<SEQ, 256>>>(norm2_w, w_router);
    k_scan<<<1, 32>>>();
    k_scatter<<<(SEQ + 255) / 256, 256>>>();
    k_moe_gemm1<<<dim3(NE * 16, FF / 128), 256, SMEM_DUAL_B>>>(w_gateup);
    k_moe_gemm2<<<dim3(NE * 32, HID / 128), 128, SMEM_M64>>>(w_down);
    k_combine<<<SEQ, 192>>>(out);
}

// round 16
// speedup vs baseline: 2.0087x; 1.1276x over previous
#include <cuda_runtime.h>
#include <math.h>

// ---------------------------------------------------------------------------
// Constants
// ---------------------------------------------------------------------------
#define SEQ   2048
#define HID   768
#define NQ    12
#define NKV   3
#define HD    64
#define QKVC  1152
#define NE    16
#define FF    1536
#define SLOTS 4096

// GEMM smem geometry
#define SA_STRIDE 20
#define SB_STRIDE 136          // 8c+8ni+g -> conflict-free B frags
#define SA64_STAGE (64 * SA_STRIDE)
#define SB_STAGE   (16 * SB_STRIDE)
#define SMEM_M64      ((3 * SA64_STAGE + 3 * SB_STAGE) * 4)
#define SMEM_M64_DUAL ((3 * SA64_STAGE + 6 * SB_STAGE) * 4)

// ---------------------------------------------------------------------------
// Device scratch
// ---------------------------------------------------------------------------
__device__ float g_xn1[SEQ * HID];
__device__ float g_Q[NQ * SEQ * HD];
__device__ float g_K[NKV * SEQ * HD];
__device__ float g_V[NKV * SEQ * HD];
__device__ float g_attn[SEQ * HID];
__device__ float g_h1[SEQ * HID];
__device__ float g_xn2[SEQ * HID];
__device__ float g_cos[SEQ * 32];
__device__ float g_sin[SEQ * 32];
__device__ int   g_eid[SLOTS];
__device__ float g_ew[SLOTS];
__device__ int   g_cnt[NE];
__device__ int   g_off[NE + 1];
__device__ int   g_cur[NE];
__device__ int   g_ptok[SLOTS];
__device__ int   g_tslot[SLOTS];
__device__ float g_Hact[(size_t)SLOTS * FF];
__device__ float g_Dn[(size_t)SLOTS * HID];

// ---------------------------------------------------------------------------
// Helpers
// ---------------------------------------------------------------------------
__device__ __forceinline__ void mma_tf32(float d[4], const unsigned a[4],
                                         const unsigned b[2]) {
    asm volatile(
        "mma.sync.aligned.m16n8k8.row.col.f32.tf32.tf32.f32 "
        "{%0,%1,%2,%3}, {%4,%5,%6,%7}, {%8,%9}, {%0,%1,%2,%3};"
        : "+f"(d[0]), "+f"(d[1]), "+f"(d[2]), "+f"(d[3])
        : "r"(a[0]), "r"(a[1]), "r"(a[2]), "r"(a[3]),
          "r"(b[0]), "r"(b[1]));
}

__device__ __forceinline__ void cp16(void* smem_dst, const void* gmem_src, bool pred) {
    unsigned d = (unsigned)__cvta_generic_to_shared(smem_dst);
    int sz = pred ? 16 : 0;
    asm volatile("cp.async.cg.shared.global [%0], [%1], 16, %2;"
                 :: "r"(d), "l"(gmem_src), "r"(sz) : "memory");
}

// ---------------------------------------------------------------------------
// RoPE table
// ---------------------------------------------------------------------------
__global__ void k_ropetab(void) {
    int idx = blockIdx.x * blockDim.x + threadIdx.x;
    int s = idx >> 5, i = idx & 31;
    float inv = powf(10000.f, -(float)(2 * i) / 64.f);
    float sn, cs;
    sincosf((float)s * inv, &sn, &cs);
    g_cos[idx] = cs;
    g_sin[idx] = sn;
}

// ---------------------------------------------------------------------------
// RMSNorm 1
// ---------------------------------------------------------------------------
__global__ void k_rmsnorm1(const float* __restrict__ x, const float* __restrict__ w) {
    int row = blockIdx.x;
    const float* xr = x + (size_t)row * HID;
    float s = 0.f;
    for (int i = threadIdx.x; i < HID; i += 256) {
        float v = xr[i];
        s += v * v;
    }
    __shared__ float red[256];
    red[threadIdx.x] = s;
    __syncthreads();
    for (int o = 128; o > 0; o >>= 1) {
        if (threadIdx.x < o) red[threadIdx.x] += red[threadIdx.x + o];
        __syncthreads();
    }
    float scale = rsqrtf(red[0] / (float)HID + 1e-6f);
    for (int i = threadIdx.x; i < HID; i += 256)
        g_xn1[(size_t)row * HID + i] = xr[i] * scale * w[i];
}

// ---------------------------------------------------------------------------
// M64 single-B TF32 GEMM core: 64x128 tile, 128 threads (4 warps, 1x4),
// 3-stage cp.async.
// ---------------------------------------------------------------------------
__device__ __forceinline__ void gemm_m64(
    const float* Ar0, const float* Ar1, bool p0, bool p1,
    const float* Br, int ldb,
    int K, unsigned* SA, unsigned* SB, float acc[4][4][4])
{
    int tid = threadIdx.x;
    int wn = tid >> 5;
    int lane = tid & 31;
    int g = lane >> 2, c = lane & 3;
    int ar0 = tid >> 2, ar1 = ar0 + 32;
    int akq = (tid & 3) * 4;
    int bkr = tid >> 5;
    int bc4 = (tid & 31) * 4;
    const float* Brp = Br + (size_t)bkr * ldb + bc4;

#define STM64(s, k0)                                                          \
    do {                                                                      \
        unsigned* a_ = SA + (s) * SA64_STAGE;                                 \
        unsigned* b_ = SB + (s) * SB_STAGE;                                   \
        cp16(a_ + ar0 * SA_STRIDE + akq, Ar0 + (k0), p0);                     \
        cp16(a_ + ar1 * SA_STRIDE + akq, Ar1 + (k0), p1);                     \
        cp16(b_ + (bkr + 0) * SB_STRIDE + bc4, Brp + (size_t)(k0) * ldb, true);         \
        cp16(b_ + (bkr + 4) * SB_STRIDE + bc4, Brp + (size_t)((k0) + 4) * ldb, true);   \
        cp16(b_ + (bkr + 8) * SB_STRIDE + bc4, Brp + (size_t)((k0) + 8) * ldb, true);   \
        cp16(b_ + (bkr + 12) * SB_STRIDE + bc4, Brp + (size_t)((k0) + 12) * ldb, true); \
        asm volatile("cp.async.commit_group;" ::: "memory");                  \
    } while (0)

    STM64(0, 0);
    STM64(1, 16);
    int buf = 0;
    for (int k0 = 0; k0 < K; k0 += 16) {
        if (k0 + 32 < K) {
            asm volatile("cp.async.wait_group 1;" ::: "memory");
            __syncthreads();
            STM64(buf == 0 ? 2 : buf - 1, k0 + 32);
        } else {
            asm volatile("cp.async.wait_group 0;" ::: "memory");
            __syncthreads();
        }
        unsigned* a_ = SA + buf * SA64_STAGE;
        unsigned* b_ = SB + buf * SB_STAGE;
#pragma unroll
        for (int kk = 0; kk < 16; kk += 8) {
            unsigned af[4][4];
#pragma unroll
            for (int mi = 0; mi < 4; mi++) {
                int m = mi * 16;
                af[mi][0] = a_[(m + g) * SA_STRIDE + kk + c];
                af[mi][1] = a_[(m + g + 8) * SA_STRIDE + kk + c];
                af[mi][2] = a_[(m + g) * SA_STRIDE + kk + c + 4];
                af[mi][3] = a_[(m + g + 8) * SA_STRIDE + kk + c + 4];
            }
#pragma unroll
            for (int ni = 0; ni < 4; ni++) {
                int n = wn * 32 + ni * 8 + g;
                unsigned bf[2];
                bf[0] = b_[(kk + c) * SB_STRIDE + n];
                bf[1] = b_[(kk + c + 4) * SB_STRIDE + n];
#pragma unroll
                for (int mi = 0; mi < 4; mi++)
                    mma_tf32(acc[mi][ni], af[mi], bf);
            }
        }
        buf = (buf == 2) ? 0 : buf + 1;
    }
#undef STM64
}

// ---------------------------------------------------------------------------
// M64 dual-B TF32 GEMM core: 64x(128+128) tile, 128 threads.
// A fragments shared across both B panels. ~3 CTAs/SM.
// ---------------------------------------------------------------------------
__device__ __forceinline__ void gemm_m64_dual(
    const float* Ar0, const float* Ar1, bool p0, bool p1,
    const float* B0r, const float* B1r, int ldb,
    int K, unsigned* SA, unsigned* SB0, unsigned* SB1,
    float accg[4][4][4], float accu[4][4][4])
{
    int tid = threadIdx.x;
    int wn = tid >> 5;
    int lane = tid & 31;
    int g = lane >> 2, c = lane & 3;
    int ar0 = tid >> 2, ar1 = ar0 + 32;
    int akq = (tid & 3) * 4;
    int bkr = tid >> 5;
    int bc4 = (tid & 31) * 4;
    const float* B0p = B0r + (size_t)bkr * ldb + bc4;
    const float* B1p = B1r + (size_t)bkr * ldb + bc4;

#define STM64D(s, k0)                                                         \
    do {                                                                      \
        unsigned* a_  = SA + (s) * SA64_STAGE;                                \
        unsigned* b0_ = SB0 + (s) * SB_STAGE;                                 \
        unsigned* b1_ = SB1 + (s) * SB_STAGE;                                 \
        cp16(a_ + ar0 * SA_STRIDE + akq, Ar0 + (k0), p0);                     \
        cp16(a_ + ar1 * SA_STRIDE + akq, Ar1 + (k0), p1);                     \
        cp16(b0_ + (bkr + 0) * SB_STRIDE + bc4, B0p + (size_t)(k0) * ldb, true);         \
        cp16(b0_ + (bkr + 4) * SB_STRIDE + bc4, B0p + (size_t)((k0) + 4) * ldb, true);   \
        cp16(b0_ + (bkr + 8) * SB_STRIDE + bc4, B0p + (size_t)((k0) + 8) * ldb, true);   \
        cp16(b0_ + (bkr + 12) * SB_STRIDE + bc4, B0p + (size_t)((k0) + 12) * ldb, true); \
        cp16(b1_ + (bkr + 0) * SB_STRIDE + bc4, B1p + (size_t)(k0) * ldb, true);         \
        cp16(b1_ + (bkr + 4) * SB_STRIDE + bc4, B1p + (size_t)((k0) + 4) * ldb, true);   \
        cp16(b1_ + (bkr + 8) * SB_STRIDE + bc4, B1p + (size_t)((k0) + 8) * ldb, true);   \
        cp16(b1_ + (bkr + 12) * SB_STRIDE + bc4, B1p + (size_t)((k0) + 12) * ldb, true); \
        asm volatile("cp.async.commit_group;" ::: "memory");                  \
    } while (0)

    STM64D(0, 0);
    STM64D(1, 16);
    int buf = 0;
    for (int k0 = 0; k0 < K; k0 += 16) {
        if (k0 + 32 < K) {
            asm volatile("cp.async.wait_group 1;" ::: "memory");
            __syncthreads();
            STM64D(buf == 0 ? 2 : buf - 1, k0 + 32);
        } else {
            asm volatile("cp.async.wait_group 0;" ::: "memory");
            __syncthreads();
        }
        unsigned* a_  = SA + buf * SA64_STAGE;
        unsigned* b0_ = SB0 + buf * SB_STAGE;
        unsigned* b1_ = SB1 + buf * SB_STAGE;
#pragma unroll
        for (int kk = 0; kk < 16; kk += 8) {
            unsigned af[4][4];
#pragma unroll
            for (int mi = 0; mi < 4; mi++) {
                int m = mi * 16;
                af[mi][0] = a_[(m + g) * SA_STRIDE + kk + c];
                af[mi][1] = a_[(m + g + 8) * SA_STRIDE + kk + c];
                af[mi][2] = a_[(m + g) * SA_STRIDE + kk + c + 4];
                af[mi][3] = a_[(m + g + 8) * SA_STRIDE + kk + c + 4];
            }
#pragma unroll
            for (int ni = 0; ni < 4; ni++) {
                int n = wn * 32 + ni * 8 + g;
                unsigned bf0[2], bf1[2];
                bf0[0] = b0_[(kk + c) * SB_STRIDE + n];
                bf0[1] = b0_[(kk + c + 4) * SB_STRIDE + n];
                bf1[0] = b1_[(kk + c) * SB_STRIDE + n];
                bf1[1] = b1_[(kk + c + 4) * SB_STRIDE + n];
#pragma unroll
                for (int mi = 0; mi < 4; mi++) {
                    mma_tf32(accg[mi][ni], af[mi], bf0);
                    mma_tf32(accu[mi][ni], af[mi], bf1);
                }
            }
        }
        buf = (buf == 2) ? 0 : buf + 1;
    }
#undef STM64D
}

// ---------------------------------------------------------------------------
// QKV projection (M64) + fused RoPE epilogue -> g_Q / g_K / g_V
// ---------------------------------------------------------------------------
__global__ void __launch_bounds__(128) k_gemm_qkv(const float* __restrict__ W) {
    extern __shared__ unsigned dsm[];
    int mb = blockIdx.x, nb = blockIdx.y;
    int tid = threadIdx.x;
    float acc[4][4][4] = {};
    {
        int ar0 = tid >> 2, ar1 = ar0 + 32;
        int akq = (tid & 3) * 4;
        const float* A = g_xn1 + (size_t)mb * 64 * HID;
        gemm_m64(A + (size_t)ar0 * HID + akq, A + (size_t)ar1 * HID + akq,
                 true, true, W + nb * 128, QKVC, HID,
                 dsm, dsm + 3 * SA64_STAGE, acc);
    }
    int wn = tid >> 5, lane = tid & 31;
    int g = lane >> 2, c = lane & 3;
#pragma unroll
    for (int mi = 0; mi < 4; mi++) {
#pragma unroll
        for (int ni = 0; ni < 4; ni++) {
            int r   = mb * 64 + mi * 16 + g;
            int col = nb * 128 + wn * 32 + ni * 8 + 2 * c;
            int dm  = col & 63;
            int pi  = dm >> 1;
            float a0 = acc[mi][ni][0], a1 = acc[mi][ni][1];
            float b0 = acc[mi][ni][2], b1 = acc[mi][ni][3];
            if (col < NQ * HD) {
                int hh = col >> 6;
                float cs0 = g_cos[r * 32 + pi],       sn0 = g_sin[r * 32 + pi];
                float cs1 = g_cos[(r + 8) * 32 + pi], sn1 = g_sin[(r + 8) * 32 + pi];
                float* d0 = g_Q + ((size_t)hh * SEQ + r) * HD + dm;
                float* d1 = g_Q + ((size_t)hh * SEQ + r + 8) * HD + dm;
                *reinterpret_cast<float2*>(d0) = make_float2(a0 * cs0 - a1 * sn0, a0 * sn0 + a1 * cs0);
                *reinterpret_cast<float2*>(d1) = make_float2(b0 * cs1 - b1 * sn1, b0 * sn1 + b1 * cs1);
            } else if (col < (NQ + NKV) * HD) {
                int hh = (col - NQ * HD) >> 6;
                float cs0 = g_cos[r * 32 + pi],       sn0 = g_sin[r * 32 + pi];
                float cs1 = g_cos[(r + 8) * 32 + pi], sn1 = g_sin[(r + 8) * 32 + pi];
                float* d0 = g_K + ((size_t)hh * SEQ + r) * HD + dm;
                float* d1 = g_K + ((size_t)hh * SEQ + r + 8) * HD + dm;
                *reinterpret_cast<float2*>(d0) = make_float2(a0 * cs0 - a1 * sn0, a0 * sn0 + a1 * cs0);
                *reinterpret_cast<float2*>(d1) = make_float2(b0 * cs1 - b1 * sn1, b0 * sn1 + b1 * cs1);
            } else {
                int hh = (col - (NQ + NKV) * HD) >> 6;
                float* d0 = g_V + ((size_t)hh * SEQ + r) * HD + dm;
                float* d1 = g_V + ((size_t)hh * SEQ + r + 8) * HD + dm;
                *reinterpret_cast<float2*>(d0) = make_float2(a0, a1);
                *reinterpret_cast<float2*>(d1) = make_float2(b0, b1);
            }
        }
    }
}

// ---------------------------------------------------------------------------
// Out projection + residual (M64): g_h1 = x + g_attn @ w_out
// ---------------------------------------------------------------------------
__global__ void __launch_bounds__(128) k_gemm_out(const float* __restrict__ W,
                                                  const float* __restrict__ xres) {
    extern __shared__ unsigned dsm[];
    int mb = blockIdx.x, nb = blockIdx.y;
    int tid = threadIdx.x;
    float acc[4][4][4] = {};
    {
        int ar0 = tid >> 2, ar1 = ar0 + 32;
        int akq = (tid & 3) * 4;
        const float* A = g_attn + (size_t)mb * 64 * HID;
        gemm_m64(A + (size_t)ar0 * HID + akq, A + (size_t)ar1 * HID + akq,
                 true, true, W + nb * 128, HID, HID,
                 dsm, dsm + 3 * SA64_STAGE, acc);
    }
    int wn = tid >> 5, lane = tid & 31;
    int g = lane >> 2, c = lane & 3;
#pragma unroll
    for (int mi = 0; mi < 4; mi++) {
#pragma unroll
        for (int ni = 0; ni < 4; ni++) {
            int r = mb * 64 + mi * 16 + g;
            int col = nb * 128 + wn * 32 + ni * 8 + 2 * c;
            size_t o0 = (size_t)r * HID + col;
            size_t o1 = (size_t)(r + 8) * HID + col;
            float2 x0 = *reinterpret_cast<const float2*>(xres + o0);
            float2 x1 = *reinterpret_cast<const float2*>(xres + o1);
            *reinterpret_cast<float2*>(g_h1 + o0) =
                make_float2(x0.x + acc[mi][ni][0], x0.y + acc[mi][ni][1]);
            *reinterpret_cast<float2*>(g_h1 + o1) =
                make_float2(x1.x + acc[mi][ni][2], x1.y + acc[mi][ni][3]);
        }
    }
}

// ---------------------------------------------------------------------------
// MoE GEMM1 (M64 dual-B, indirect A rows via ptok) fused with SiLU*up
// ---------------------------------------------------------------------------
__global__ void __launch_bounds__(128) k_moe_gemm1(const float* __restrict__ Wgu) {
    extern __shared__ unsigned dsm[];
    __shared__ int sptok[64];
    int e = blockIdx.x >> 5, mb = blockIdx.x & 31, nb = blockIdx.y;
    int r0 = g_off[e];
    int rows_e = g_off[e + 1] - r0;
    int rbase = mb * 64;
    if (rbase >= rows_e) return;
    int rows = min(64, rows_e - rbase);
    int tid = threadIdx.x;
    if (tid < 64) sptok[tid] = (tid < rows) ? g_ptok[r0 + rbase + tid] : 0;
    __syncthreads();

    float accg[4][4][4] = {};
    float accu[4][4][4] = {};
    {
        int ar0 = tid >> 2, ar1 = ar0 + 32;
        int akq = (tid & 3) * 4;
        bool p0 = ar0 < rows, p1 = ar1 < rows;
        const float* Ar0 = g_xn2 + (size_t)sptok[ar0] * HID + akq;
        const float* Ar1 = g_xn2 + (size_t)sptok[ar1] * HID + akq;
        const float* Bg = Wgu + (size_t)e * HID * (2 * FF) + nb * 128;
        const float* Bu = Bg + FF;
        gemm_m64_dual(Ar0, Ar1, p0, p1, Bg, Bu, 2 * FF, HID,
                      dsm, dsm + 3 * SA64_STAGE, dsm + 3 * SA64_STAGE + 3 * SB_STAGE,
                      accg, accu);
    }
    int wn = tid >> 5, lane = tid & 31;
    int g = lane >> 2, c = lane & 3;
    float* Cp = g_Hact + (size_t)(r0 + rbase) * FF + nb * 128;
#pragma unroll
    for (int mi = 0; mi < 4; mi++) {
#pragma unroll
        for (int ni = 0; ni < 4; ni++) {
            int rr = mi * 16 + g;
            int col = wn * 32 + ni * 8 + 2 * c;
            float h[4];
#pragma unroll
            for (int j = 0; j < 4; j++) {
                float gv = accg[mi][ni][j];
                h[j] = gv / (1.f + __expf(-gv)) * accu[mi][ni][j];
            }
            if (rr < rows)
                *reinterpret_cast<float2*>(Cp + (size_t)rr * FF + col) =
                    make_float2(h[0], h[1]);
            if (rr + 8 < rows)
                *reinterpret_cast<float2*>(Cp + (size_t)(rr + 8) * FF + col) =
                    make_float2(h[2], h[3]);
        }
    }
}

// ---------------------------------------------------------------------------
// MoE GEMM2 (M64): Dn[slot] = Hact[slot] @ w_down[e]
// ---------------------------------------------------------------------------
__global__ void __launch_bounds__(128) k_moe_gemm2(const float* __restrict__ Wd) {
    extern __shared__ unsigned dsm[];
    int e = blockIdx.x >> 5, mb = blockIdx.x & 31, nb = blockIdx.y;
    int r0 = g_off[e];
    int rows_e = g_off[e + 1] - r0;
    int rbase = mb * 64;
    if (rbase >= rows_e) return;
    int rows = min(64, rows_e - rbase);
    int tid = threadIdx.x;
    float acc[4][4][4] = {};
    {
        int ar0 = tid >> 2, ar1 = ar0 + 32;
        int akq = (tid & 3) * 4;
        bool p0 = ar0 < rows, p1 = ar1 < rows;
        const float* A = g_Hact + (size_t)(r0 + rbase) * FF;
        const float* Ar0 = A + (size_t)(p0 ? ar0 : 0) * FF + akq;
        const float* Ar1 = A + (size_t)(p1 ? ar1 : 0) * FF + akq;
        gemm_m64(Ar0, Ar1, p0, p1,
                 Wd + (size_t)e * FF * HID + nb * 128, HID, FF,
                 dsm, dsm + 3 * SA64_STAGE, acc);
    }
    int wn = tid >> 5, lane = tid & 31;
    int g = lane >> 2, c = lane & 3;
    float* Cp = g_Dn + (size_t)(r0 + rbase) * HID + nb * 128;
#pragma unroll
    for (int mi = 0; mi < 4; mi++) {
#pragma unroll
        for (int ni = 0; ni < 4; ni++) {
            int rr = mi * 16 + g;
            int col = wn * 32 + ni * 8 + 2 * c;
            if (rr < rows)
                *reinterpret_cast<float2*>(Cp + (size_t)rr * HID + col) =
                    make_float2(acc[mi][ni][0], acc[mi][ni][1]);
            if (rr + 8 < rows)
                *reinterpret_cast<float2*>(Cp + (size_t)(rr + 8) * HID + col) =
                    make_float2(acc[mi][ni][2], acc[mi][ni][3]);
        }
    }
}

// ---------------------------------------------------------------------------
// Flash attention (unchanged): TF32, double-buffered K/V, P aliases S.
// ---------------------------------------------------------------------------
#define ATT_W (4 * (64 * 68) + 2 * (64 * 72) + 3 * 64)
#define ATT_SMEM_BYTES (ATT_W * 4)

__global__ void k_attn(void) {
    extern __shared__ unsigned smu[];
    unsigned* uQ  = smu;
    unsigned* uK0 = uQ + 64 * 68;
    unsigned* uK1 = uK0 + 64 * 68;
    unsigned* uSP = uK1 + 64 * 68;
    unsigned* uV0 = uSP + 64 * 68;
    unsigned* uV1 = uV0 + 64 * 72;
    float* mrow  = (float*)(uV1 + 64 * 72);
    float* lrow  = mrow + 64;
    float* arow  = lrow + 64;

    int qb = gridDim.x - 1 - blockIdx.x;
    int h  = blockIdx.y;
    int kvh = h >> 2;
    int tid = threadIdx.x;
    int warp = tid >> 5, lane = tid & 31;
    int wm = warp >> 2, wn = warp & 3;
    int g  = lane >> 2, c = lane & 3;

    const float* Kbase = g_K + (size_t)kvh * SEQ * HD;
    const float* Vbase = g_V + (size_t)kvh * SEQ * HD;

#define ATT_ISSUE(buf_, kb_)                                                  \
    do {                                                                      \
        unsigned* dK = (buf_) ? uK1 : uK0;                                    \
        unsigned* dV = (buf_) ? uV1 : uV0;                                    \
        const float* Kb_ = Kbase + (size_t)(kb_) * 64 * HD;                   \
        const float* Vb_ = Vbase + (size_t)(kb_) * 64 * HD;                   \
        _Pragma("unroll")                                                     \
        for (int it = 0; it < 4; it++) {                                      \
            int e_ = tid + it * 256;                                          \
            int r_ = e_ >> 4;                                                 \
            int q_ = (e_ & 15) * 4;                                           \
            cp16(dK + r_ * 68 + q_, Kb_ + r_ * HD + q_, true);                \
            cp16(dV + r_ * 72 + q_, Vb_ + r_ * HD + q_, true);                \
        }                                                                     \
        asm volatile("cp.async.commit_group;" ::: "memory");                  \
    } while (0)

    ATT_ISSUE(0, 0);
    if (qb > 0) ATT_ISSUE(1, 1);

    const float* Qb = g_Q + ((size_t)h * SEQ + qb * 64) * HD;
    for (int e = tid; e < 4096; e += 256) {
        int r = e >> 6, d = e & 63;
        uQ[r * 68 + d] = __float_as_uint(Qb[r * HD + d] * 0.125f);
    }
    if (tid < 64) { mrow[tid] = -1e30f; lrow[tid] = 0.f; }

    float oacc[2][2][4] = {};
    for (int kb = 0; kb <= qb; kb++) {
        int buf = kb & 1;
        if (kb < qb)
            asm volatile("cp.async.wait_group 1;" ::: "memory");
        else
            asm volatile("cp.async.wait_group 0;" ::: "memory");
        __syncthreads();
        unsigned* cK = buf ? uK1 : uK0;
        unsigned* cV = buf ? uV1 : uV0;

        float sacc[2][2][4] = {};
#pragma unroll
        for (int kk = 0; kk < 64; kk += 8) {
            unsigned af[2][4];
#pragma unroll
            for (int mi = 0; mi < 2; mi++) {
                int m = wm * 32 + mi * 16;
                af[mi][0] = uQ[(m + g) * 68 + kk + c];
                af[mi][1] = uQ[(m + g + 8) * 68 + kk + c];
                af[mi][2] = uQ[(m + g) * 68 + kk + c + 4];
                af[mi][3] = uQ[(m + g + 8) * 68 + kk + c + 4];
            }
#pragma unroll
            for (int ni = 0; ni < 2; ni++) {
                int n = wn * 16 + ni * 8 + g;
                unsigned bf[2];
                bf[0] = cK[n * 68 + kk + c];
                bf[1] = cK[n * 68 + kk + c + 4];
#pragma unroll
                for (int mi = 0; mi < 2; mi++)
                    mma_tf32(sacc[mi][ni], af[mi], bf);
            }
        }
        bool diag = (kb == qb);
#pragma unroll
        for (int mi = 0; mi < 2; mi++) {
#pragma unroll
            for (int ni = 0; ni < 2; ni++) {
                int r0 = wm * 32 + mi * 16 + g;
                int cl = wn * 16 + ni * 8 + 2 * c;
                float v0 = sacc[mi][ni][0], v1 = sacc[mi][ni][1];
                float v2 = sacc[mi][ni][2], v3 = sacc[mi][ni][3];
                if (diag) {
                    if (cl > r0)     v0 = -1e30f;
                    if (cl + 1 > r0) v1 = -1e30f;
                    if (cl > r0 + 8)     v2 = -1e30f;
                    if (cl + 1 > r0 + 8) v3 = -1e30f;
                }
                uSP[r0 * 68 + cl]           = __float_as_uint(v0);
                uSP[r0 * 68 + cl + 1]       = __float_as_uint(v1);
                uSP[(r0 + 8) * 68 + cl]     = __float_as_uint(v2);
                uSP[(r0 + 8) * 68 + cl + 1] = __float_as_uint(v3);
            }
        }
        __syncthreads();

        {
            int i  = tid >> 2;
            int jq = (tid & 3) * 16;
            float sv[16];
            float mx = -1e30f;
#pragma unroll
            for (int j = 0; j < 16; j++) {
                sv[j] = __uint_as_float(uSP[i * 68 + jq + j]);
                mx = fmaxf(mx, sv[j]);
            }
            mx = fmaxf(mx, __shfl_xor_sync(0xffffffffu, mx, 1));
            mx = fmaxf(mx, __shfl_xor_sync(0xffffffffu, mx, 2));
            float mold = mrow[i];
            mx = fmaxf(mx, mold);
            float sum = 0.f;
#pragma unroll
            for (int j = 0; j < 16; j++) {
                float p = __expf(sv[j] - mx);
                uSP[i * 68 + jq + j] = __float_as_uint(p);
                sum += p;
            }
            sum += __shfl_xor_sync(0xffffffffu, sum, 1);
            sum += __shfl_xor_sync(0xffffffffu, sum, 2);
            if ((tid & 3) == 0) {
                float al = __expf(mold - mx);
                lrow[i] = lrow[i] * al + sum;
                mrow[i] = mx;
                arow[i] = al;
            }
        }
        __syncthreads();

#pragma unroll
        for (int mi = 0; mi < 2; mi++) {
            float a0 = arow[wm * 32 + mi * 16 + g];
            float a1 = arow[wm * 32 + mi * 16 + g + 8];
#pragma unroll
            for (int ni = 0; ni < 2; ni++) {
                oacc[mi][ni][0] *= a0;
                oacc[mi][ni][1] *= a0;
                oacc[mi][ni][2] *= a1;
                oacc[mi][ni][3] *= a1;
            }
        }
#pragma unroll
        for (int kk = 0; kk < 64; kk += 8) {
            unsigned af[2][4];
#pragma unroll
            for (int mi = 0; mi < 2; mi++) {
                int m = wm * 32 + mi * 16;
                af[mi][0] = uSP[(m + g) * 68 + kk + c];
                af[mi][1] = uSP[(m + g + 8) * 68 + kk + c];
                af[mi][2] = uSP[(m + g) * 68 + kk + c + 4];
                af[mi][3] = uSP[(m + g + 8) * 68 + kk + c + 4];
            }
#pragma unroll
            for (int ni = 0; ni < 2; ni++) {
                int n = wn * 16 + ni * 8 + g;
                unsigned bf[2];
                bf[0] = cV[(kk + c) * 72 + n];
                bf[1] = cV[(kk + c + 4) * 72 + n];
#pragma unroll
                for (int mi = 0; mi < 2; mi++)
                    mma_tf32(oacc[mi][ni], af[mi], bf);
            }
        }
        if (kb + 2 <= qb) {
            __syncthreads();
            ATT_ISSUE(buf, kb + 2);
        }
    }

    __syncthreads();
#pragma unroll
    for (int mi = 0; mi < 2; mi++) {
        int rl0 = wm * 32 + mi * 16 + g;
        float i0 = 1.f / lrow[rl0];
        float i1 = 1.f / lrow[rl0 + 8];
        int gr0 = qb * 64 + rl0;
#pragma unroll
        for (int ni = 0; ni < 2; ni++) {
            int col = h * HD + wn * 16 + ni * 8 + 2 * c;
            *reinterpret_cast<float2*>(g_attn + (size_t)gr0 * HID + col) =
                make_float2(oacc[mi][ni][0] * i0, oacc[mi][ni][1] * i0);
            *reinterpret_cast<float2*>(g_attn + (size_t)(gr0 + 8) * HID + col) =
                make_float2(oacc[mi][ni][2] * i1, oacc[mi][ni][3] * i1);
        }
    }
#undef ATT_ISSUE
}

// ---------------------------------------------------------------------------
// Fused RMSNorm2 + router (fp32)
// ---------------------------------------------------------------------------
__global__ void k_rms2router(const float* __restrict__ w, const float* __restrict__ Wr) {
    int t = blockIdx.x;
    int tid = threadIdx.x;
    __shared__ float sxn[HID];
    __shared__ float red[256];
    __shared__ float lg[NE];
    const float* xr = g_h1 + (size_t)t * HID;
    float s = 0.f;
    for (int i = tid; i < HID; i += 256) {
        float v = xr[i];
        s += v * v;
    }
    red[tid] = s;
    __syncthreads();
    for (int o = 128; o > 0; o >>= 1) {
        if (tid < o) red[tid] += red[tid + o];
        __syncthreads();
    }
    float scale = rsqrtf(red[0] / (float)HID + 1e-6f);
    for (int i = tid; i < HID; i += 256) {
        float v = xr[i] * scale * w[i];
        sxn[i] = v;
        g_xn2[(size_t)t * HID + i] = v;
    }
    __syncthreads();
    int warp = tid >> 5, lane = tid & 31;
    float s0 = 0.f, s1 = 0.f;
    for (int k = lane; k < HID; k += 32) {
        float xv = sxn[k];
        s0 += xv * Wr[k * NE + 2 * warp];
        s1 += xv * Wr[k * NE + 2 * warp + 1];
    }
#pragma unroll
    for (int o = 16; o > 0; o >>= 1) {
        s0 += __shfl_xor_sync(0xffffffffu, s0, o);
        s1 += __shfl_xor_sync(0xffffffffu, s1, o);
    }
    if (lane == 0) { lg[2 * warp] = s0; lg[2 * warp + 1] = s1; }
    __syncthreads();
    if (tid == 0) {
        int b0 = 0;
        float v0 = lg[0];
        for (int e = 1; e < NE; e++)
            if (lg[e] > v0) { v0 = lg[e]; b0 = e; }
        int b1 = -1;
        float v1 = -3e38f;
        for (int e = 0; e < NE; e++)
            if (e != b0 && lg[e] > v1) { v1 = lg[e]; b1 = e; }
        float w0 = 1.f / (1.f + __expf(v1 - v0));
        g_eid[2 * t] = b0;
        g_eid[2 * t + 1] = b1;
        g_ew[2 * t] = w0;
        g_ew[2 * t + 1] = 1.f - w0;
        atomicAdd(&g_cnt[b0], 1);
        atomicAdd(&g_cnt[b1], 1);
    }
}

// ---------------------------------------------------------------------------
// Routing plumbing
// ---------------------------------------------------------------------------
__global__ void k_reset(void) {
    if (threadIdx.x < NE) {
        g_cnt[threadIdx.x] = 0;
        g_cur[threadIdx.x] = 0;
    }
}

__global__ void k_scan(void) {
    if (threadIdx.x == 0) {
        int a = 0;
        for (int e = 0; e < NE; e++) {
            g_off[e] = a;
            a += g_cnt[e];
        }
        g_off[NE] = a;
    }
}

__global__ void k_scatter(void) {
    int t = blockIdx.x * blockDim.x + threadIdx.x;
    if (t >= SEQ) return;
#pragma unroll
    for (int slot = 0; slot < 2; slot++) {
        int e = g_eid[2 * t + slot];
        int pos = g_off[e] + atomicAdd(&g_cur[e], 1);
        g_ptok[pos] = t;
        g_tslot[2 * t + slot] = pos;
    }
}

__global__ void k_combine(float* __restrict__ out) {
    int t = blockIdx.x;
    int i = threadIdx.x;
    int p0 = g_tslot[2 * t], p1 = g_tslot[2 * t + 1];
    float w0 = g_ew[2 * t], w1 = g_ew[2 * t + 1];
    float4 a = reinterpret_cast<const float4*>(g_h1 + (size_t)t * HID)[i];
    float4 b = reinterpret_cast<const float4*>(g_Dn + (size_t)p0 * HID)[i];
    float4 c = reinterpret_cast<const float4*>(g_Dn + (size_t)p1 * HID)[i];
    float4 o = make_float4(a.x + w0 * b.x + w1 * c.x,
                           a.y + w0 * b.y + w1 * c.y,
                           a.z + w0 * b.z + w1 * c.z,
                           a.w + w0 * b.w + w1 * c.w);
    reinterpret_cast<float4*>(out + (size_t)t * HID)[i] = o;
}

// ---------------------------------------------------------------------------
// Launch
// ---------------------------------------------------------------------------
extern "C" void kernel_launch(void* const* d_in, const int* in_sizes, int n_in,
                              void* d_out, int out_size) {
    (void)in_sizes; (void)n_in; (void)out_size;
    const float* x        = (const float*)d_in[0];
    const float* norm1_w  = (const float*)d_in[1];
    const float* w_qkv    = (const float*)d_in[2];
    const float* w_out    = (const float*)d_in[3];
    const float* norm2_w  = (const float*)d_in[4];
    const float* w_router = (const float*)d_in[5];
    const float* w_gateup = (const float*)d_in[6];
    const float* w_down   = (const float*)d_in[7];
    float* out = (float*)d_out;

    cudaFuncSetAttribute(k_attn, cudaFuncAttributeMaxDynamicSharedMemorySize,
                         ATT_SMEM_BYTES);
    cudaFuncSetAttribute(k_gemm_qkv, cudaFuncAttributeMaxDynamicSharedMemorySize,
                         SMEM_M64);
    cudaFuncSetAttribute(k_gemm_out, cudaFuncAttributeMaxDynamicSharedMemorySize,
                         SMEM_M64);
    cudaFuncSetAttribute(k_moe_gemm1, cudaFuncAttributeMaxDynamicSharedMemorySize,
                         SMEM_M64_DUAL);
    cudaFuncSetAttribute(k_moe_gemm2, cudaFuncAttributeMaxDynamicSharedMemorySize,
                         SMEM_M64);

    k_reset<<<1, 32>>>();
    k_ropetab<<<SEQ * 32 / 256, 256>>>();
    k_rmsnorm1<<<SEQ, 256>>>(x, norm1_w);
    k_gemm_qkv<<<dim3(SEQ / 64, QKVC / 128), 128, SMEM_M64>>>(w_qkv);
    k_attn<<<dim3(SEQ / 64, NQ), 256, ATT_SMEM_BYTES>>>();
    k_gemm_out<<<dim3(SEQ / 64, HID / 128), 128, SMEM_M64>>>(w_out, x);
    k_rms2router<<<SEQ, 256>>>(norm2_w, w_router);
    k_scan<<<1, 32>>>();
    k_scatter<<<(SEQ + 255) / 256, 256>>>();
    k_moe_gemm1<<<dim3(NE * 32, FF / 128), 128, SMEM_M64_DUAL>>>(w_gateup);
    k_moe_gemm2<<<dim3(NE * 32, HID / 128), 128, SMEM_M64>>>(w_down);
    k_combine<<<SEQ, 192>>>(out);
}